// round 5
// baseline (speedup 1.0000x reference)
#include <cuda_runtime.h>
#include <cuda_bf16.h>
#include <cstdint>

// Problem dims
#define BB 64
#define TT 128
#define SS 128
#define CC 512
#define HH 8
#define DHH 64
#define FFF 2048
#define LL 6
#define LN_EPS 1e-5f

typedef unsigned long long ull;

// ---------------- scratch (static device allocations — allowed) --------------
__device__ float g_x[BB * TT * CC];        // current activations
__device__ float g_q[BB * HH * TT * DHH];
__device__ float g_k[BB * HH * TT * DHH];
__device__ float g_v[BB * HH * TT * DHH];
__device__ float g_att[BB * TT * CC];      // attention / ff output
__device__ float g_h[BB * TT * FFF];       // ff hidden

// ---------------- packed f32x2 helpers (B300: FFMA2 = 2x fp32 rate) ----------
__device__ __forceinline__ ull ffma2(ull a, ull b, ull c) {
    ull d;
    asm("fma.rn.f32x2 %0, %1, %2, %3;" : "=l"(d) : "l"(a), "l"(b), "l"(c));
    return d;
}
__device__ __forceinline__ ull splat2(float x) {
    ull d;
    asm("mov.b64 %0, {%1, %1};" : "=l"(d) : "f"(x));
    return d;
}
__device__ __forceinline__ float2 unpack2(ull v) {
    float2 r;
    asm("mov.b64 {%0, %1}, %2;" : "=f"(r.x), "=f"(r.y) : "l"(v));
    return r;
}

// =============================================================================
// GEMM 128x128 tile, fp32 via f32x2. A: [M,K] row-major (lda), B: [K,N] row-major (ldb).
// out = relu?(A@B + bias (+ residual))
// =============================================================================
__global__ __launch_bounds__(256, 2) void gemm128(
    const float* __restrict__ A, int lda,
    const float* __restrict__ Bm, int ldb,
    const float* __restrict__ bias,
    const float* __restrict__ res,   // may be nullptr, leading dim = ldo
    float* __restrict__ outp, int ldo,
    int K, int do_relu)
{
    __shared__ float As[16][132];   // transposed: As[k][m]
    __shared__ float Bs[16][132];   // Bs[k][n]

    const int tid = threadIdx.x;
    const int m0 = blockIdx.x * 128;
    const int n0 = blockIdx.y * 128;
    const int tx = tid & 15, ty = tid >> 4;
    const int mt = ty * 8, nt = tx * 8;

    ull acc[8][4];
#pragma unroll
    for (int i = 0; i < 8; i++)
#pragma unroll
        for (int j = 0; j < 4; j++) acc[i][j] = 0ull;

    const int am = tid >> 1;
    const int ak = (tid & 1) * 8;
    const float* Ap = A + (size_t)(m0 + am) * lda + ak;
    const int bk = tid >> 4;
    const int bn = (tid & 15) * 8;
    const float* Bp = Bm + (size_t)bk * ldb + n0 + bn;

    for (int k0 = 0; k0 < K; k0 += 16) {
        float4 a0 = *(const float4*)(Ap + k0);
        float4 a1 = *(const float4*)(Ap + k0 + 4);
        float4 b0 = *(const float4*)(Bp + (size_t)k0 * ldb);
        float4 b1 = *(const float4*)(Bp + (size_t)k0 * ldb + 4);
        __syncthreads();
        As[ak + 0][am] = a0.x; As[ak + 1][am] = a0.y;
        As[ak + 2][am] = a0.z; As[ak + 3][am] = a0.w;
        As[ak + 4][am] = a1.x; As[ak + 5][am] = a1.y;
        As[ak + 6][am] = a1.z; As[ak + 7][am] = a1.w;
        *(float4*)&Bs[bk][bn] = b0;
        *(float4*)&Bs[bk][bn + 4] = b1;
        __syncthreads();
#pragma unroll
        for (int kk = 0; kk < 16; kk++) {
            float4 af0 = *(const float4*)&As[kk][mt];
            float4 af1 = *(const float4*)&As[kk][mt + 4];
            ulonglong2 bb0 = *(const ulonglong2*)&Bs[kk][nt];
            ulonglong2 bb1 = *(const ulonglong2*)&Bs[kk][nt + 4];
            ull bv0 = bb0.x, bv1 = bb0.y, bv2 = bb1.x, bv3 = bb1.y;
            float av[8] = {af0.x, af0.y, af0.z, af0.w, af1.x, af1.y, af1.z, af1.w};
#pragma unroll
            for (int i = 0; i < 8; i++) {
                ull a2 = splat2(av[i]);
                acc[i][0] = ffma2(a2, bv0, acc[i][0]);
                acc[i][1] = ffma2(a2, bv1, acc[i][1]);
                acc[i][2] = ffma2(a2, bv2, acc[i][2]);
                acc[i][3] = ffma2(a2, bv3, acc[i][3]);
            }
        }
    }

#pragma unroll
    for (int i = 0; i < 8; i++) {
        int r = m0 + mt + i;
        float* orow = outp + (size_t)r * ldo + n0 + nt;
        const float* rrow = res ? (res + (size_t)r * ldo + n0 + nt) : nullptr;
#pragma unroll
        for (int j = 0; j < 4; j++) {
            float2 f = unpack2(acc[i][j]);
            int c0 = 2 * j, c1 = 2 * j + 1;
            float v0 = f.x + bias[n0 + nt + c0];
            float v1 = f.y + bias[n0 + nt + c1];
            if (rrow) { v0 += rrow[c0]; v1 += rrow[c1]; }
            if (do_relu) { v0 = fmaxf(v0, 0.f); v1 = fmaxf(v1, 0.f); }
            orow[c0] = v0;
            orow[c1] = v1;
        }
    }
}

// =============================================================================
// Per-head QKV projection GEMM. Tile 128(M) x 64(N=DH), K = C = 512.
// A: [8192, 512] rows = (b,t). W (per head): [512, 64] row-major.
// out[b,h,t,d] = A@W + bias.  grid = (64 Mtiles, H, 3 projections)
// =============================================================================
__global__ __launch_bounds__(256, 2) void gemm_proj(
    const float* __restrict__ Aq, const float* __restrict__ Akv,
    const float* __restrict__ Wq, const float* __restrict__ Wk, const float* __restrict__ Wv,
    const float* __restrict__ bq, const float* __restrict__ bk2, const float* __restrict__ bv,
    float* __restrict__ Oq, float* __restrict__ Ok, float* __restrict__ Ov)
{
    const int z = blockIdx.z;
    const int h = blockIdx.y;
    const float* A = (z == 0) ? Aq : Akv;
    const float* W = (z == 0) ? Wq : (z == 1 ? Wk : Wv);
    const float* bias = (z == 0) ? bq : (z == 1 ? bk2 : bv);
    float* O = (z == 0) ? Oq : (z == 1 ? Ok : Ov);
    W += (size_t)h * CC * DHH;
    bias += h * DHH;

    __shared__ float As[16][132];
    __shared__ float Bs[16][68];

    const int tid = threadIdx.x;
    const int m0 = blockIdx.x * 128;
    const int tx = tid & 15, ty = tid >> 4;
    const int mt = ty * 8, nt = tx * 4;

    ull acc[8][2];
#pragma unroll
    for (int i = 0; i < 8; i++) { acc[i][0] = 0ull; acc[i][1] = 0ull; }

    const int am = tid >> 1;
    const int ak = (tid & 1) * 8;
    const float* Ap = A + (size_t)(m0 + am) * CC + ak;
    const int lbk = tid >> 4;
    const int lbn = (tid & 15) * 4;
    const float* Bp = W + (size_t)lbk * DHH + lbn;

    for (int k0 = 0; k0 < CC; k0 += 16) {
        float4 a0 = *(const float4*)(Ap + k0);
        float4 a1 = *(const float4*)(Ap + k0 + 4);
        float4 b0 = *(const float4*)(Bp + (size_t)k0 * DHH);
        __syncthreads();
        As[ak + 0][am] = a0.x; As[ak + 1][am] = a0.y;
        As[ak + 2][am] = a0.z; As[ak + 3][am] = a0.w;
        As[ak + 4][am] = a1.x; As[ak + 5][am] = a1.y;
        As[ak + 6][am] = a1.z; As[ak + 7][am] = a1.w;
        *(float4*)&Bs[lbk][lbn] = b0;
        __syncthreads();
#pragma unroll
        for (int kk = 0; kk < 16; kk++) {
            float4 af0 = *(const float4*)&As[kk][mt];
            float4 af1 = *(const float4*)&As[kk][mt + 4];
            ulonglong2 bb = *(const ulonglong2*)&Bs[kk][nt];
            float av[8] = {af0.x, af0.y, af0.z, af0.w, af1.x, af1.y, af1.z, af1.w};
#pragma unroll
            for (int i = 0; i < 8; i++) {
                ull a2 = splat2(av[i]);
                acc[i][0] = ffma2(a2, bb.x, acc[i][0]);
                acc[i][1] = ffma2(a2, bb.y, acc[i][1]);
            }
        }
    }

#pragma unroll
    for (int i = 0; i < 8; i++) {
        int r = m0 + mt + i;
        int b = r >> 7;          // r / T
        int t = r & 127;         // r % T
        float* orow = O + ((size_t)(b * HH + h) * TT + t) * DHH + nt;
#pragma unroll
        for (int j = 0; j < 2; j++) {
            float2 f = unpack2(acc[i][j]);
            orow[2 * j]     = f.x + bias[nt + 2 * j];
            orow[2 * j + 1] = f.y + bias[nt + 2 * j + 1];
        }
    }
}

// =============================================================================
// Attention: one CTA per (b,h). 128 threads, thread t owns query row t.
// smem: KV tile (reused for K then V) + P scores (stride 129 -> conflict-free).
// =============================================================================
__global__ __launch_bounds__(128) void attn_kernel(
    const float* __restrict__ Q, const float* __restrict__ K,
    const float* __restrict__ V, float* __restrict__ outp)
{
    extern __shared__ float sm[];
    float* KV = sm;             // 128*64 floats
    float* P = sm + TT * DHH;   // 128*129 floats

    const int bh = blockIdx.x;
    const int t = threadIdx.x;
    const size_t base = (size_t)bh * TT * DHH;
    const float* Qp = Q + base;
    const float* Kp = K + base;
    const float* Vp = V + base;

    // load K tile
    for (int i = t * 4; i < TT * DHH; i += 128 * 4)
        *(float4*)&KV[i] = *(const float4*)&Kp[i];

    // q row into regs (16 x ulonglong2 = 64 floats)
    ulonglong2 q2[16];
    const ulonglong2* qsrc = (const ulonglong2*)(Qp + (size_t)t * DHH);
#pragma unroll
    for (int i = 0; i < 16; i++) q2[i] = qsrc[i];
    __syncthreads();

    float* Prow = P + t * 129;
    float mx = -1e30f;
    for (int s = 0; s < SS; s++) {
        const ulonglong2* kp2 = (const ulonglong2*)(KV + s * DHH);
        ull a0 = 0, a1 = 0, a2v = 0, a3 = 0;
#pragma unroll
        for (int i = 0; i < 16; i += 2) {
            ulonglong2 kv0 = kp2[i], kv1 = kp2[i + 1];
            a0 = ffma2(q2[i].x, kv0.x, a0);
            a1 = ffma2(q2[i].y, kv0.y, a1);
            a2v = ffma2(q2[i + 1].x, kv1.x, a2v);
            a3 = ffma2(q2[i + 1].y, kv1.y, a3);
        }
        float2 f0 = unpack2(a0), f1 = unpack2(a1), f2 = unpack2(a2v), f3 = unpack2(a3);
        float dot = ((f0.x + f0.y) + (f1.x + f1.y)) + ((f2.x + f2.y) + (f3.x + f3.y));
        Prow[s] = dot;
        mx = fmaxf(mx, dot);
    }
    float sum = 0.f;
    for (int s = 0; s < SS; s++) {
        float e = __expf(0.125f * (Prow[s] - mx));
        Prow[s] = e;
        sum += e;
    }
    float inv = 1.f / sum;

    __syncthreads();   // all done reading K
    // load V tile over K
    for (int i = t * 4; i < TT * DHH; i += 128 * 4)
        *(float4*)&KV[i] = *(const float4*)&Vp[i];
    __syncthreads();

    ull o2[32];
#pragma unroll
    for (int i = 0; i < 32; i++) o2[i] = 0ull;
    for (int s = 0; s < SS; s++) {
        ull p2 = splat2(Prow[s]);
        const ulonglong2* vp2 = (const ulonglong2*)(KV + s * DHH);
#pragma unroll
        for (int i = 0; i < 16; i++) {
            ulonglong2 vv = vp2[i];
            o2[2 * i]     = ffma2(p2, vv.x, o2[2 * i]);
            o2[2 * i + 1] = ffma2(p2, vv.y, o2[2 * i + 1]);
        }
    }

    const int b = bh / HH, h = bh % HH;
    float* op = outp + ((size_t)b * TT + t) * CC + h * DHH;
#pragma unroll
    for (int j = 0; j < 32; j++) {
        float2 f = unpack2(o2[j]);
        op[2 * j]     = f.x * inv;
        op[2 * j + 1] = f.y * inv;
    }
}

// =============================================================================
// Joint (T,C) LayerNorm per batch element, fused residual add: out = LN(a + r)
// grid = B, block = 256. r may be nullptr. out may alias a.
// =============================================================================
__global__ __launch_bounds__(256) void ln2d_kernel(
    const float* __restrict__ a, const float* __restrict__ r, float* __restrict__ outp)
{
    const int bidx = blockIdx.x;
    const size_t off = (size_t)bidx * TT * CC;
    const float4* pa = (const float4*)(a + off);
    const float4* pr = r ? (const float4*)(r + off) : nullptr;
    const int n4 = TT * CC / 4;   // 16384

    float s = 0.f, ss = 0.f;
    for (int i = threadIdx.x; i < n4; i += 256) {
        float4 v = pa[i];
        if (pr) { float4 w = pr[i]; v.x += w.x; v.y += w.y; v.z += w.z; v.w += w.w; }
        s += (v.x + v.y) + (v.z + v.w);
        ss += (v.x * v.x + v.y * v.y) + (v.z * v.z + v.w * v.w);
    }
#pragma unroll
    for (int o = 16; o > 0; o >>= 1) {
        s += __shfl_down_sync(0xffffffffu, s, o);
        ss += __shfl_down_sync(0xffffffffu, ss, o);
    }
    __shared__ float rs[8], rss[8], stats[2];
    const int w = threadIdx.x >> 5;
    if ((threadIdx.x & 31) == 0) { rs[w] = s; rss[w] = ss; }
    __syncthreads();
    if (threadIdx.x == 0) {
        float S = 0.f, SSg = 0.f;
        for (int i = 0; i < 8; i++) { S += rs[i]; SSg += rss[i]; }
        const float N = (float)(TT * CC);
        float mu = S / N;
        float var = SSg / N - mu * mu;
        stats[0] = mu;
        stats[1] = rsqrtf(var + LN_EPS);
    }
    __syncthreads();
    const float mu = stats[0], rsig = stats[1];
    float4* po = (float4*)(outp + off);
    for (int i = threadIdx.x; i < n4; i += 256) {
        float4 v = pa[i];
        if (pr) { float4 wv = pr[i]; v.x += wv.x; v.y += wv.y; v.z += wv.z; v.w += wv.w; }
        v.x = (v.x - mu) * rsig;
        v.y = (v.y - mu) * rsig;
        v.z = (v.z - mu) * rsig;
        v.w = (v.w - mu) * rsig;
        po[i] = v;
    }
}

// =============================================================================
extern "C" void kernel_launch(void* const* d_in, const int* in_sizes, int n_in,
                              void* d_out, int out_size)
{
    (void)in_sizes; (void)n_in; (void)out_size;

    const float* x_in  = (const float*)d_in[0];
    const float* enc   = (const float*)d_in[1];
    const float* sa_wq = (const float*)d_in[2];
    const float* sa_bq = (const float*)d_in[3];
    const float* sa_wk = (const float*)d_in[4];
    const float* sa_bk = (const float*)d_in[5];
    const float* sa_wv = (const float*)d_in[6];
    const float* sa_bv = (const float*)d_in[7];
    const float* ca_wq = (const float*)d_in[8];
    const float* ca_bq = (const float*)d_in[9];
    const float* ca_wk = (const float*)d_in[10];
    const float* ca_bk = (const float*)d_in[11];
    const float* ca_wv = (const float*)d_in[12];
    const float* ca_bv = (const float*)d_in[13];
    const float* ff_w1 = (const float*)d_in[14];
    const float* ff_b1 = (const float*)d_in[15];
    const float* ff_w2 = (const float*)d_in[16];
    const float* ff_b2 = (const float*)d_in[17];

    float *gx, *gq, *gk, *gv, *gatt, *gh;
    cudaGetSymbolAddress((void**)&gx, g_x);
    cudaGetSymbolAddress((void**)&gq, g_q);
    cudaGetSymbolAddress((void**)&gk, g_k);
    cudaGetSymbolAddress((void**)&gv, g_v);
    cudaGetSymbolAddress((void**)&gatt, g_att);
    cudaGetSymbolAddress((void**)&gh, g_h);

    const int attn_smem = (TT * DHH + TT * 129) * (int)sizeof(float);  // 98816
    cudaFuncSetAttribute(attn_kernel, cudaFuncAttributeMaxDynamicSharedMemorySize, attn_smem);

    cudaMemcpyAsync(gx, x_in, sizeof(float) * BB * TT * CC, cudaMemcpyDeviceToDevice);

    for (int l = 0; l < LL; l++) {
        const size_t woff = (size_t)l * HH * CC * DHH;
        const size_t boff = (size_t)l * HH * DHH;

        // ---- self attention ----
        gemm_proj<<<dim3(64, HH, 3), 256>>>(
            gx, gx,
            sa_wq + woff, sa_wk + woff, sa_wv + woff,
            sa_bq + boff, sa_bk + boff, sa_bv + boff,
            gq, gk, gv);
        attn_kernel<<<BB * HH, 128, attn_smem>>>(gq, gk, gv, gatt);
        ln2d_kernel<<<BB, 256>>>(gx, gatt, gx);

        // ---- cross attention (k/v from encoder output) ----
        gemm_proj<<<dim3(64, HH, 3), 256>>>(
            gx, enc,
            ca_wq + woff, ca_wk + woff, ca_wv + woff,
            ca_bq + boff, ca_bk + boff, ca_bv + boff,
            gq, gk, gv);
        attn_kernel<<<BB * HH, 128, attn_smem>>>(gq, gk, gv, gatt);
        ln2d_kernel<<<BB, 256>>>(gx, gatt, gx);

        // ---- feed forward ----
        gemm128<<<dim3(64, FFF / 128), 256>>>(
            gx, CC, ff_w1 + (size_t)l * CC * FFF, FFF,
            ff_b1 + (size_t)l * FFF, nullptr, gh, FFF, CC, 1);
        gemm128<<<dim3(64, CC / 128), 256>>>(
            gh, FFF, ff_w2 + (size_t)l * FFF * CC, CC,
            ff_b2 + (size_t)l * CC, gx, gatt, CC, FFF, 0);
        ln2d_kernel<<<BB, 256>>>(gatt, nullptr, gx);
    }

    cudaMemcpyAsync(d_out, gx, sizeof(float) * BB * TT * CC, cudaMemcpyDeviceToDevice);
}

// round 7
// speedup vs baseline: 1.7168x; 1.7168x over previous
#include <cuda_runtime.h>
#include <cuda_bf16.h>
#include <cstdint>

// Problem dims
#define BB 64
#define TT 128
#define SS 128
#define CC 512
#define HH 8
#define DHH 64
#define FFF 2048
#define LL 6
#define LN_EPS 1e-5f

typedef unsigned long long ull;

// ---------------- scratch (static device allocations — allowed) --------------
__device__ float g_x[BB * TT * CC];
__device__ float g_q[BB * HH * TT * DHH];
__device__ float g_k[BB * HH * TT * DHH];
__device__ float g_v[BB * HH * TT * DHH];
__device__ float g_att[BB * TT * CC];
__device__ float g_h[BB * TT * FFF];
__device__ __nv_bfloat16 g_whi[2048 * 2048 / 2];   // 1,048,576 els (max N*K)
__device__ __nv_bfloat16 g_wlo[2048 * 2048 / 2];
__device__ float g_bias[2048];

// ---------------- packed f32x2 helpers ---------------------------------------
__device__ __forceinline__ ull ffma2(ull a, ull b, ull c) {
    ull d; asm("fma.rn.f32x2 %0, %1, %2, %3;" : "=l"(d) : "l"(a), "l"(b), "l"(c));
    return d;
}
__device__ __forceinline__ ull splat2(float x) {
    ull d; asm("mov.b64 %0, {%1, %1};" : "=l"(d) : "f"(x)); return d;
}
__device__ __forceinline__ float2 unpack2(ull v) {
    float2 r; asm("mov.b64 {%0, %1}, %2;" : "=f"(r.x), "=f"(r.y) : "l"(v)); return r;
}

__device__ __forceinline__ uint32_t smem_u32(const void* p) {
    uint32_t a;
    asm("{ .reg .u64 t; cvta.to.shared.u64 t, %1; cvt.u32.u64 %0, t; }" : "=r"(a) : "l"(p));
    return a;
}
__device__ __forceinline__ uint32_t bfu(__nv_bfloat16 v) {
    return (uint32_t)__bfloat16_as_ushort(v);
}

// ---------------- mma.sync / ldmatrix (plain-sm_103-safe PTX) ----------------
#define LDX4(r0, r1, r2, r3, addr) \
    asm volatile("ldmatrix.sync.aligned.m8n8.x4.shared.b16 {%0,%1,%2,%3}, [%4];" \
                 : "=r"(r0), "=r"(r1), "=r"(r2), "=r"(r3) : "r"(addr))

__device__ __forceinline__ void mma16816(float* c, const uint32_t* a, const uint32_t* b) {
    asm volatile(
        "mma.sync.aligned.m16n8k16.row.col.f32.bf16.bf16.f32 "
        "{%0,%1,%2,%3}, {%4,%5,%6,%7}, {%8,%9}, {%0,%1,%2,%3};"
        : "+f"(c[0]), "+f"(c[1]), "+f"(c[2]), "+f"(c[3])
        : "r"(a[0]), "r"(a[1]), "r"(a[2]), "r"(a[3]), "r"(b[0]), "r"(b[1]));
}

// =============================================================================
// HMMA split-bf16 GEMM.  CTA tile 128(M) x 128(N), BK=64, 8 warps (2x4 grid,
// warp tile 64x32).  A fp32 converted inline to hi/lo bf16; W prepped bf16
// hi/lo [N, Kdim] K-major.  3-term compensated product in fp32 accum.
// smem rows padded: 64 halves + 8 = 72 halves = 144 B stride (conflict-free
// ldmatrix: 8 rows * 144B mod 128 all distinct).
// =============================================================================
#define AR_STRIDE 144            // bytes per 64-k smem row
#define TILE_BYTES (128 * AR_STRIDE)          // 18432
#define GEMM_SMEM (4 * TILE_BYTES)            // Ahi, Alo, Bhi, Blo = 73728

__global__ __launch_bounds__(256, 1) void gemm_mma(
    const float* __restrict__ Aq, const float* __restrict__ Akv, int lda,
    const __nv_bfloat16* __restrict__ Whi, const __nv_bfloat16* __restrict__ Wlo, int Kdim,
    const float* __restrict__ bias, const float* __restrict__ res,
    float* __restrict__ outp, int ldo,
    float* __restrict__ Oq, float* __restrict__ Ok, float* __restrict__ Ov,
    int relu, int qkv)
{
    extern __shared__ char sm[];
    const uint32_t smb = smem_u32(sm);
    const int tid = threadIdx.x;
    const int wid = tid >> 5, lane = tid & 31;
    const int mw = wid >> 2, nw = wid & 3;

    const int m0 = blockIdx.x * 128;
    const int n0 = blockIdx.y * 128;
    const float* A = (qkv && n0 >= 512) ? Akv : Aq;
    A += (size_t)m0 * lda;
    const __nv_bfloat16* Bh = Whi + (size_t)n0 * Kdim;
    const __nv_bfloat16* Bl = Wlo + (size_t)n0 * Kdim;

    float acc[4][4][4];
#pragma unroll
    for (int i = 0; i < 4; i++)
#pragma unroll
        for (int j = 0; j < 4; j++)
#pragma unroll
            for (int r = 0; r < 4; r++) acc[i][j][r] = 0.f;

    // ldmatrix per-lane smem offsets
    const uint32_t sA_hi = smb;
    const uint32_t sA_lo = smb + TILE_BYTES;
    const uint32_t sB_hi = smb + 2 * TILE_BYTES;
    const uint32_t sB_lo = smb + 3 * TILE_BYTES;
    // A: lanes 0-15 -> rows, k lo-half; lanes 16-31 -> rows, k hi-half
    const int aoff = (mw * 64 + (lane & 15)) * AR_STRIDE + ((lane >> 4) * 8) * 2;
    // B: matrix idx mi = lane>>3: mi0 n0-7/k0, mi1 n0-7/k8, mi2 n8-15/k0, mi3 n8-15/k8
    const int mi = lane >> 3;
    const int n_off = ((mi >> 1) * 8) + (lane & 7);
    const int k_off = (mi & 1) * 8;
    const int boff = (nw * 32 + n_off) * AR_STRIDE + k_off * 2;

    const int nch = Kdim >> 6;
    for (int c = 0; c < nch; c++) {
        const int kc0 = c << 6;
        __syncthreads();
        // ---- A tile: 128 x 64 fp32 -> bf16 hi/lo ----
#pragma unroll
        for (int p = 0; p < 8; p++) {
            int v = p * 256 + tid;
            int row = v >> 4, kq = v & 15;
            float4 a = *(const float4*)(A + (size_t)row * lda + kc0 + kq * 4);
            __nv_bfloat16 h0 = __float2bfloat16_rn(a.x), h1 = __float2bfloat16_rn(a.y);
            __nv_bfloat16 h2 = __float2bfloat16_rn(a.z), h3 = __float2bfloat16_rn(a.w);
            uint2 uh;
            uh.x = bfu(h0) | (bfu(h1) << 16);
            uh.y = bfu(h2) | (bfu(h3) << 16);
            float l0 = a.x - __bfloat162float(h0), l1 = a.y - __bfloat162float(h1);
            float l2 = a.z - __bfloat162float(h2), l3 = a.w - __bfloat162float(h3);
            uint2 ul;
            ul.x = bfu(__float2bfloat16_rn(l0)) | (bfu(__float2bfloat16_rn(l1)) << 16);
            ul.y = bfu(__float2bfloat16_rn(l2)) | (bfu(__float2bfloat16_rn(l3)) << 16);
            int so = row * AR_STRIDE + kq * 8;
            *(uint2*)(sm + so) = uh;
            *(uint2*)(sm + TILE_BYTES + so) = ul;
        }
        // ---- B tiles: 128 x 64 bf16 hi/lo (already [N,K] K-major) ----
#pragma unroll
        for (int p = 0; p < 4; p++) {
            int v = p * 256 + tid;
            int row = v >> 3, j = v & 7;
            size_t go = (size_t)row * Kdim + kc0 + j * 8;
            int so = row * AR_STRIDE + j * 16;
            *(uint4*)(sm + 2 * TILE_BYTES + so) = *(const uint4*)(Bh + go);
            *(uint4*)(sm + 3 * TILE_BYTES + so) = *(const uint4*)(Bl + go);
        }
        __syncthreads();

#pragma unroll
        for (int kk = 0; kk < 4; kk++) {
            uint32_t bh[4][2], bl[4][2];
            LDX4(bh[0][0], bh[0][1], bh[1][0], bh[1][1], sB_hi + boff + kk * 32);
            LDX4(bh[2][0], bh[2][1], bh[3][0], bh[3][1], sB_hi + boff + 2304 + kk * 32);
            LDX4(bl[0][0], bl[0][1], bl[1][0], bl[1][1], sB_lo + boff + kk * 32);
            LDX4(bl[2][0], bl[2][1], bl[3][0], bl[3][1], sB_lo + boff + 2304 + kk * 32);
#pragma unroll
            for (int i = 0; i < 4; i++) {
                uint32_t ah[4], al[4];
                LDX4(ah[0], ah[1], ah[2], ah[3], sA_hi + aoff + i * 2304 + kk * 32);
                LDX4(al[0], al[1], al[2], al[3], sA_lo + aoff + i * 2304 + kk * 32);
#pragma unroll
                for (int j = 0; j < 4; j++) {
                    mma16816(acc[i][j], ah, bh[j]);
                    mma16816(acc[i][j], ah, bl[j]);
                    mma16816(acc[i][j], al, bh[j]);
                }
            }
        }
    }

    // ---- epilogue ----
    const int gid = lane >> 2, tg = lane & 3;
#pragma unroll
    for (int i = 0; i < 4; i++) {
#pragma unroll
        for (int j = 0; j < 4; j++) {
            int row0 = m0 + mw * 64 + i * 16 + gid;
            int row1 = row0 + 8;
            int col = n0 + nw * 32 + j * 8 + tg * 2;
            float b0v = bias[col], b1v = bias[col + 1];
            float v00 = acc[i][j][0] + b0v, v01 = acc[i][j][1] + b1v;
            float v10 = acc[i][j][2] + b0v, v11 = acc[i][j][3] + b1v;
            if (!qkv) {
                if (res) {
                    float2 r0 = *(const float2*)(res + (size_t)row0 * ldo + col);
                    float2 r1 = *(const float2*)(res + (size_t)row1 * ldo + col);
                    v00 += r0.x; v01 += r0.y; v10 += r1.x; v11 += r1.y;
                }
                if (relu) {
                    v00 = fmaxf(v00, 0.f); v01 = fmaxf(v01, 0.f);
                    v10 = fmaxf(v10, 0.f); v11 = fmaxf(v11, 0.f);
                }
                *(float2*)(outp + (size_t)row0 * ldo + col) = make_float2(v00, v01);
                *(float2*)(outp + (size_t)row1 * ldo + col) = make_float2(v10, v11);
            } else {
                const int z = col >> 9, hh = (col >> 6) & 7, d0 = col & 63;
                float* O = (z == 0) ? Oq : (z == 1 ? Ok : Ov);
                int b0i = row0 >> 7, t0 = row0 & 127;
                int b1i = row1 >> 7, t1 = row1 & 127;
                *(float2*)(O + (((size_t)(b0i * HH + hh)) * TT + t0) * DHH + d0) = make_float2(v00, v01);
                *(float2*)(O + (((size_t)(b1i * HH + hh)) * TT + t1) * DHH + d0) = make_float2(v10, v11);
            }
        }
    }
}

// =============================================================================
// Weight prep: transpose fp32 weights into K-major bf16 hi/lo [N,K]
// =============================================================================
__global__ __launch_bounds__(256) void prep_qkv(
    const float* __restrict__ wq, const float* __restrict__ wk, const float* __restrict__ wv,
    const float* __restrict__ bq, const float* __restrict__ bk, const float* __restrict__ bv,
    __nv_bfloat16* __restrict__ whi, __nv_bfloat16* __restrict__ wlo, float* __restrict__ gb)
{
    __shared__ float smt[64][65];
    const int tid = threadIdx.x;
    const int c0 = blockIdx.x * 64;
    const int nb0 = blockIdx.y * 64;
    const int z = nb0 >> 9, hh = (nb0 >> 6) & 7;
    const float* W = ((z == 0) ? wq : (z == 1 ? wk : wv)) + (size_t)hh * CC * DHH;

#pragma unroll
    for (int p = 0; p < 4; p++) {
        int v = p * 256 + tid;
        int ci = v >> 4, q = v & 15;
        float4 a = *(const float4*)(W + (size_t)(c0 + ci) * DHH + q * 4);
        smt[ci][q * 4 + 0] = a.x; smt[ci][q * 4 + 1] = a.y;
        smt[ci][q * 4 + 2] = a.z; smt[ci][q * 4 + 3] = a.w;
    }
    __syncthreads();
#pragma unroll
    for (int p = 0; p < 2; p++) {
        int u = p * 256 + tid;
        int d = u >> 3, cv = u & 7;
        uint4 uh, ul;
        uint32_t* ph = (uint32_t*)&uh;
        uint32_t* pl = (uint32_t*)&ul;
#pragma unroll
        for (int j = 0; j < 4; j++) {
            float x0 = smt[cv * 8 + 2 * j][d], x1 = smt[cv * 8 + 2 * j + 1][d];
            __nv_bfloat16 h0 = __float2bfloat16_rn(x0), h1 = __float2bfloat16_rn(x1);
            ph[j] = bfu(h0) | (bfu(h1) << 16);
            float l0 = x0 - __bfloat162float(h0), l1 = x1 - __bfloat162float(h1);
            pl[j] = bfu(__float2bfloat16_rn(l0)) | (bfu(__float2bfloat16_rn(l1)) << 16);
        }
        size_t o = (size_t)(nb0 + d) * CC + c0 + cv * 8;
        *(uint4*)(whi + o) = uh;
        *(uint4*)(wlo + o) = ul;
    }
    if (blockIdx.x == 0 && tid < 64) {
        const float* bsrc = (z == 0) ? bq : (z == 1 ? bk : bv);
        gb[nb0 + tid] = bsrc[hh * DHH + tid];
    }
}

__global__ __launch_bounds__(256) void prep_plain(
    const float* __restrict__ W, int Kd, int Nd,
    __nv_bfloat16* __restrict__ whi, __nv_bfloat16* __restrict__ wlo)
{
    __shared__ float smt[64][65];
    const int tid = threadIdx.x;
    const int c0 = blockIdx.x * 64;
    const int nb0 = blockIdx.y * 64;

#pragma unroll
    for (int p = 0; p < 4; p++) {
        int v = p * 256 + tid;
        int ci = v >> 4, q = v & 15;
        float4 a = *(const float4*)(W + (size_t)(c0 + ci) * Nd + nb0 + q * 4);
        smt[ci][q * 4 + 0] = a.x; smt[ci][q * 4 + 1] = a.y;
        smt[ci][q * 4 + 2] = a.z; smt[ci][q * 4 + 3] = a.w;
    }
    __syncthreads();
#pragma unroll
    for (int p = 0; p < 2; p++) {
        int u = p * 256 + tid;
        int d = u >> 3, cv = u & 7;
        uint4 uh, ul;
        uint32_t* ph = (uint32_t*)&uh;
        uint32_t* pl = (uint32_t*)&ul;
#pragma unroll
        for (int j = 0; j < 4; j++) {
            float x0 = smt[cv * 8 + 2 * j][d], x1 = smt[cv * 8 + 2 * j + 1][d];
            __nv_bfloat16 h0 = __float2bfloat16_rn(x0), h1 = __float2bfloat16_rn(x1);
            ph[j] = bfu(h0) | (bfu(h1) << 16);
            float l0 = x0 - __bfloat162float(h0), l1 = x1 - __bfloat162float(h1);
            pl[j] = bfu(__float2bfloat16_rn(l0)) | (bfu(__float2bfloat16_rn(l1)) << 16);
        }
        size_t o = (size_t)(nb0 + d) * Kd + c0 + cv * 8;
        *(uint4*)(whi + o) = uh;
        *(uint4*)(wlo + o) = ul;
    }
}

// =============================================================================
// Attention: one CTA per (b,h). 128 threads, thread t owns query row t.
// =============================================================================
__global__ __launch_bounds__(128) void attn_kernel(
    const float* __restrict__ Q, const float* __restrict__ K,
    const float* __restrict__ V, float* __restrict__ outp)
{
    extern __shared__ float smf[];
    float* KV = smf;
    float* P = smf + TT * DHH;

    const int bh = blockIdx.x;
    const int t = threadIdx.x;
    const size_t base = (size_t)bh * TT * DHH;
    const float* Qp = Q + base;
    const float* Kp = K + base;
    const float* Vp = V + base;

    for (int i = t * 4; i < TT * DHH; i += 128 * 4)
        *(float4*)&KV[i] = *(const float4*)&Kp[i];

    ulonglong2 q2[16];
    const ulonglong2* qsrc = (const ulonglong2*)(Qp + (size_t)t * DHH);
#pragma unroll
    for (int i = 0; i < 16; i++) q2[i] = qsrc[i];
    __syncthreads();

    float* Prow = P + t * 129;
    float mx = -1e30f;
    for (int s = 0; s < SS; s++) {
        const ulonglong2* kp2 = (const ulonglong2*)(KV + s * DHH);
        ull a0 = 0, a1 = 0, a2v = 0, a3 = 0;
#pragma unroll
        for (int i = 0; i < 16; i += 2) {
            ulonglong2 kv0 = kp2[i], kv1 = kp2[i + 1];
            a0 = ffma2(q2[i].x, kv0.x, a0);
            a1 = ffma2(q2[i].y, kv0.y, a1);
            a2v = ffma2(q2[i + 1].x, kv1.x, a2v);
            a3 = ffma2(q2[i + 1].y, kv1.y, a3);
        }
        float2 f0 = unpack2(a0), f1 = unpack2(a1), f2 = unpack2(a2v), f3 = unpack2(a3);
        float dot = ((f0.x + f0.y) + (f1.x + f1.y)) + ((f2.x + f2.y) + (f3.x + f3.y));
        Prow[s] = dot;
        mx = fmaxf(mx, dot);
    }
    float sum = 0.f;
    for (int s = 0; s < SS; s++) {
        float e = __expf(0.125f * (Prow[s] - mx));
        Prow[s] = e;
        sum += e;
    }
    float inv = 1.f / sum;

    __syncthreads();
    for (int i = t * 4; i < TT * DHH; i += 128 * 4)
        *(float4*)&KV[i] = *(const float4*)&Vp[i];
    __syncthreads();

    ull o2[32];
#pragma unroll
    for (int i = 0; i < 32; i++) o2[i] = 0ull;
    for (int s = 0; s < SS; s++) {
        ull p2 = splat2(Prow[s]);
        const ulonglong2* vp2 = (const ulonglong2*)(KV + s * DHH);
#pragma unroll
        for (int i = 0; i < 16; i++) {
            ulonglong2 vv = vp2[i];
            o2[2 * i]     = ffma2(p2, vv.x, o2[2 * i]);
            o2[2 * i + 1] = ffma2(p2, vv.y, o2[2 * i + 1]);
        }
    }

    const int b = bh / HH, h = bh % HH;
    float* op = outp + ((size_t)b * TT + t) * CC + h * DHH;
#pragma unroll
    for (int j = 0; j < 32; j++) {
        float2 f = unpack2(o2[j]);
        op[2 * j]     = f.x * inv;
        op[2 * j + 1] = f.y * inv;
    }
}

// =============================================================================
// Joint (T,C) LayerNorm per batch element, fused residual: out = LN(a + r)
// =============================================================================
__global__ __launch_bounds__(256) void ln2d_kernel(
    const float* __restrict__ a, const float* __restrict__ r, float* __restrict__ outp)
{
    const int bidx = blockIdx.x;
    const size_t off = (size_t)bidx * TT * CC;
    const float4* pa = (const float4*)(a + off);
    const float4* pr = r ? (const float4*)(r + off) : nullptr;
    const int n4 = TT * CC / 4;

    float s = 0.f, ss = 0.f;
    for (int i = threadIdx.x; i < n4; i += 256) {
        float4 v = pa[i];
        if (pr) { float4 w = pr[i]; v.x += w.x; v.y += w.y; v.z += w.z; v.w += w.w; }
        s += (v.x + v.y) + (v.z + v.w);
        ss += (v.x * v.x + v.y * v.y) + (v.z * v.z + v.w * v.w);
    }
#pragma unroll
    for (int o = 16; o > 0; o >>= 1) {
        s += __shfl_down_sync(0xffffffffu, s, o);
        ss += __shfl_down_sync(0xffffffffu, ss, o);
    }
    __shared__ float rs[8], rss[8], stats[2];
    const int w = threadIdx.x >> 5;
    if ((threadIdx.x & 31) == 0) { rs[w] = s; rss[w] = ss; }
    __syncthreads();
    if (threadIdx.x == 0) {
        float S = 0.f, SSg = 0.f;
        for (int i = 0; i < 8; i++) { S += rs[i]; SSg += rss[i]; }
        const float N = (float)(TT * CC);
        float mu = S / N;
        float var = SSg / N - mu * mu;
        stats[0] = mu;
        stats[1] = rsqrtf(var + LN_EPS);
    }
    __syncthreads();
    const float mu = stats[0], rsig = stats[1];
    float4* po = (float4*)(outp + off);
    for (int i = threadIdx.x; i < n4; i += 256) {
        float4 v = pa[i];
        if (pr) { float4 wv = pr[i]; v.x += wv.x; v.y += wv.y; v.z += wv.z; v.w += wv.w; }
        v.x = (v.x - mu) * rsig;
        v.y = (v.y - mu) * rsig;
        v.z = (v.z - mu) * rsig;
        v.w = (v.w - mu) * rsig;
        po[i] = v;
    }
}

// =============================================================================
extern "C" void kernel_launch(void* const* d_in, const int* in_sizes, int n_in,
                              void* d_out, int out_size)
{
    (void)in_sizes; (void)n_in; (void)out_size;

    const float* x_in  = (const float*)d_in[0];
    const float* enc   = (const float*)d_in[1];
    const float* sa_wq = (const float*)d_in[2];
    const float* sa_bq = (const float*)d_in[3];
    const float* sa_wk = (const float*)d_in[4];
    const float* sa_bk = (const float*)d_in[5];
    const float* sa_wv = (const float*)d_in[6];
    const float* sa_bv = (const float*)d_in[7];
    const float* ca_wq = (const float*)d_in[8];
    const float* ca_bq = (const float*)d_in[9];
    const float* ca_wk = (const float*)d_in[10];
    const float* ca_bk = (const float*)d_in[11];
    const float* ca_wv = (const float*)d_in[12];
    const float* ca_bv = (const float*)d_in[13];
    const float* ff_w1 = (const float*)d_in[14];
    const float* ff_b1 = (const float*)d_in[15];
    const float* ff_w2 = (const float*)d_in[16];
    const float* ff_b2 = (const float*)d_in[17];

    float *gx, *gq, *gk, *gv, *gatt, *gh, *gb;
    __nv_bfloat16 *gwhi, *gwlo;
    cudaGetSymbolAddress((void**)&gx, g_x);
    cudaGetSymbolAddress((void**)&gq, g_q);
    cudaGetSymbolAddress((void**)&gk, g_k);
    cudaGetSymbolAddress((void**)&gv, g_v);
    cudaGetSymbolAddress((void**)&gatt, g_att);
    cudaGetSymbolAddress((void**)&gh, g_h);
    cudaGetSymbolAddress((void**)&gwhi, g_whi);
    cudaGetSymbolAddress((void**)&gwlo, g_wlo);
    cudaGetSymbolAddress((void**)&gb, g_bias);

    const int attn_smem = (TT * DHH + TT * 129) * (int)sizeof(float);
    cudaFuncSetAttribute(attn_kernel, cudaFuncAttributeMaxDynamicSharedMemorySize, attn_smem);
    cudaFuncSetAttribute(gemm_mma, cudaFuncAttributeMaxDynamicSharedMemorySize, GEMM_SMEM);

    cudaMemcpyAsync(gx, x_in, sizeof(float) * BB * TT * CC, cudaMemcpyDeviceToDevice);

    for (int l = 0; l < LL; l++) {
        const size_t woff = (size_t)l * HH * CC * DHH;
        const size_t boff = (size_t)l * HH * DHH;

        // ---- self attention ----
        prep_qkv<<<dim3(8, 24), 256>>>(sa_wq + woff, sa_wk + woff, sa_wv + woff,
                                       sa_bq + boff, sa_bk + boff, sa_bv + boff,
                                       gwhi, gwlo, gb);
        gemm_mma<<<dim3(64, 12), 256, GEMM_SMEM>>>(
            gx, gx, CC, gwhi, gwlo, CC, gb, nullptr, nullptr, 0,
            gq, gk, gv, 0, 1);
        attn_kernel<<<BB * HH, 128, attn_smem>>>(gq, gk, gv, gatt);
        ln2d_kernel<<<BB, 256>>>(gx, gatt, gx);

        // ---- cross attention ----
        prep_qkv<<<dim3(8, 24), 256>>>(ca_wq + woff, ca_wk + woff, ca_wv + woff,
                                       ca_bq + boff, ca_bk + boff, ca_bv + boff,
                                       gwhi, gwlo, gb);
        gemm_mma<<<dim3(64, 12), 256, GEMM_SMEM>>>(
            gx, enc, CC, gwhi, gwlo, CC, gb, nullptr, nullptr, 0,
            gq, gk, gv, 0, 1);
        attn_kernel<<<BB * HH, 128, attn_smem>>>(gq, gk, gv, gatt);
        ln2d_kernel<<<BB, 256>>>(gx, gatt, gx);

        // ---- feed forward ----
        prep_plain<<<dim3(8, 32), 256>>>(ff_w1 + (size_t)l * CC * FFF, CC, FFF, gwhi, gwlo);
        gemm_mma<<<dim3(64, 16), 256, GEMM_SMEM>>>(
            gx, gx, CC, gwhi, gwlo, CC, ff_b1 + (size_t)l * FFF, nullptr, gh, FFF,
            nullptr, nullptr, nullptr, 1, 0);
        prep_plain<<<dim3(32, 8), 256>>>(ff_w2 + (size_t)l * FFF * CC, FFF, CC, gwhi, gwlo);
        gemm_mma<<<dim3(64, 4), 256, GEMM_SMEM>>>(
            gh, gh, FFF, gwhi, gwlo, FFF, ff_b2 + (size_t)l * CC, gx, gatt, CC,
            nullptr, nullptr, nullptr, 0, 0);
        ln2d_kernel<<<BB, 256>>>(gatt, nullptr, gx);
    }

    cudaMemcpyAsync(d_out, gx, sizeof(float) * BB * TT * CC, cudaMemcpyDeviceToDevice);
}

// round 10
// speedup vs baseline: 2.0174x; 1.1751x over previous
#include <cuda_runtime.h>
#include <cuda_bf16.h>
#include <cstdint>

// Problem dims
#define BB 64
#define TT 128
#define SS 128
#define CC 512
#define HH 8
#define DHH 64
#define FFF 2048
#define LL 6
#define LN_EPS 1e-5f

typedef unsigned long long ull;
typedef __nv_bfloat16 bf16;

// ---------------- scratch (static device allocations — allowed) --------------
__device__ float g_x[BB * TT * CC];
__device__ float g_q[BB * HH * TT * DHH];
__device__ float g_k[BB * HH * TT * DHH];
__device__ float g_v[BB * HH * TT * DHH];
__device__ float g_att[BB * TT * CC];
__device__ bf16 g_xhi[BB * TT * CC];          // split activations (decoder x)
__device__ bf16 g_xlo[BB * TT * CC];
__device__ bf16 g_ehi[BB * SS * CC];          // split encoder output
__device__ bf16 g_elo[BB * SS * CC];
__device__ bf16 g_hhi[BB * TT * FFF];         // split ff hidden
__device__ bf16 g_hlo[BB * TT * FFF];
__device__ bf16 g_whi[2048 * 512];            // prepped weights (max N*K = 1M)
__device__ bf16 g_wlo[2048 * 512];
__device__ float g_bias[2048];
__device__ float g_red[BB * 8 * 2];           // LN partial sums

// ---------------- packed f32x2 helpers ---------------------------------------
__device__ __forceinline__ ull ffma2(ull a, ull b, ull c) {
    ull d; asm("fma.rn.f32x2 %0, %1, %2, %3;" : "=l"(d) : "l"(a), "l"(b), "l"(c));
    return d;
}
__device__ __forceinline__ ull splat2(float x) {
    ull d; asm("mov.b64 %0, {%1, %1};" : "=l"(d) : "f"(x)); return d;
}
__device__ __forceinline__ float2 unpack2(ull v) {
    float2 r; asm("mov.b64 {%0, %1}, %2;" : "=f"(r.x), "=f"(r.y) : "l"(v)); return r;
}
__device__ __forceinline__ uint32_t smem_u32(const void* p) {
    uint32_t a;
    asm("{ .reg .u64 t; cvta.to.shared.u64 t, %1; cvt.u32.u64 %0, t; }" : "=r"(a) : "l"(p));
    return a;
}
__device__ __forceinline__ uint32_t bfu(bf16 v) {
    return (uint32_t)__bfloat16_as_ushort(v);
}
// split one fp32 -> hi/lo bf16 pair
__device__ __forceinline__ void split1(float x, uint32_t& hi, uint32_t& lo) {
    bf16 h = __float2bfloat16_rn(x);
    hi = bfu(h);
    lo = bfu(__float2bfloat16_rn(x - __bfloat162float(h)));
}

// ---------------- mma.sync / ldmatrix / cp.async (plain-sm_103 PTX) ----------
#define LDX4(r0, r1, r2, r3, addr) \
    asm volatile("ldmatrix.sync.aligned.m8n8.x4.shared.b16 {%0,%1,%2,%3}, [%4];" \
                 : "=r"(r0), "=r"(r1), "=r"(r2), "=r"(r3) : "r"(addr))

__device__ __forceinline__ void mma16816(float* c, const uint32_t* a, const uint32_t* b) {
    asm volatile(
        "mma.sync.aligned.m16n8k16.row.col.f32.bf16.bf16.f32 "
        "{%0,%1,%2,%3}, {%4,%5,%6,%7}, {%8,%9}, {%0,%1,%2,%3};"
        : "+f"(c[0]), "+f"(c[1]), "+f"(c[2]), "+f"(c[3])
        : "r"(a[0]), "r"(a[1]), "r"(a[2]), "r"(a[3]), "r"(b[0]), "r"(b[1]));
}
__device__ __forceinline__ void cpasync16(uint32_t dst, const void* src) {
    asm volatile("cp.async.cg.shared.global [%0], [%1], 16;" :: "r"(dst), "l"(src));
}

// =============================================================================
// HMMA split-bf16 GEMM, cp.async double-buffered.
// CTA tile 128x128, BK=64, 8 warps (2x4), warp tile 64x32, 3-term compensation.
// All operands pre-split bf16, K-major rows. smem rows: 64 halves padded to
// 144B stride (conflict-free ldmatrix, 16B cp.async chunks).
// mode: 0 = fp32 out (+res,+relu)   1 = qkv scatter   2 = bf16 hi/lo out (+relu)
// =============================================================================
#define AR_STRIDE 144
#define MAT_BYTES (128 * AR_STRIDE)           // 18432
#define STAGE_BYTES (4 * MAT_BYTES)           // 73728
#define GEMM_SMEM (2 * STAGE_BYTES)           // 147456

__global__ __launch_bounds__(256, 1) void gemm_mma(
    const bf16* __restrict__ Aq_hi, const bf16* __restrict__ Aq_lo,
    const bf16* __restrict__ Akv_hi, const bf16* __restrict__ Akv_lo, int Kdim,
    const bf16* __restrict__ Whi, const bf16* __restrict__ Wlo,
    const float* __restrict__ bias, const float* __restrict__ res,
    float* __restrict__ outp, bf16* __restrict__ ohi, bf16* __restrict__ olo, int ldo,
    float* __restrict__ Oq, float* __restrict__ Ok, float* __restrict__ Ov,
    int relu, int mode)
{
    extern __shared__ char sm[];
    const uint32_t smb = smem_u32(sm);
    const int tid = threadIdx.x;
    const int wid = tid >> 5, lane = tid & 31;
    const int mw = wid >> 2, nw = wid & 3;

    const int m0 = blockIdx.x * 128;
    const int n0 = blockIdx.y * 128;
    const bf16 *Ahp, *Alp;
    if (mode == 1 && n0 >= 512) { Ahp = Akv_hi; Alp = Akv_lo; }
    else                        { Ahp = Aq_hi;  Alp = Aq_lo; }
    Ahp += (size_t)m0 * Kdim;
    Alp += (size_t)m0 * Kdim;
    const bf16* Bh = Whi + (size_t)n0 * Kdim;
    const bf16* Bl = Wlo + (size_t)n0 * Kdim;

    float acc[4][4][4];
#pragma unroll
    for (int i = 0; i < 4; i++)
#pragma unroll
        for (int j = 0; j < 4; j++)
#pragma unroll
            for (int r = 0; r < 4; r++) acc[i][j][r] = 0.f;

    // ldmatrix per-lane offsets (relative to stage base)
    const int aoff = (mw * 64 + (lane & 15)) * AR_STRIDE + ((lane >> 4) * 8) * 2;
    const int mi = lane >> 3;
    const int n_off = ((mi >> 1) * 8) + (lane & 7);
    const int k_off = (mi & 1) * 8;
    const int boff = (nw * 32 + n_off) * AR_STRIDE + k_off * 2;

    const int nch = Kdim >> 6;

    // per-thread load slots: v = p*256+tid -> row = v>>3 (0..127), c = v&7
#define LOAD_STAGE(cidx) do {                                                  \
        const uint32_t dstb = smb + (((cidx) & 1) ? STAGE_BYTES : 0);          \
        const int kc = (cidx) << 6;                                            \
        _Pragma("unroll")                                                      \
        for (int p = 0; p < 4; p++) {                                          \
            int v = p * 256 + tid;                                             \
            int row = v >> 3, cc = v & 7;                                      \
            uint32_t d = dstb + row * AR_STRIDE + cc * 16;                     \
            size_t go = (size_t)row * Kdim + kc + cc * 8;                      \
            cpasync16(d, Ahp + go);                                            \
            cpasync16(d + MAT_BYTES, Alp + go);                                \
            cpasync16(d + 2 * MAT_BYTES, Bh + go);                             \
            cpasync16(d + 3 * MAT_BYTES, Bl + go);                             \
        }                                                                      \
        asm volatile("cp.async.commit_group;");                                \
    } while (0)

    LOAD_STAGE(0);

    for (int c = 0; c < nch; c++) {
        if (c + 1 < nch) {
            LOAD_STAGE(c + 1);
            asm volatile("cp.async.wait_group 1;");
        } else {
            asm volatile("cp.async.wait_group 0;");
        }
        __syncthreads();

        const uint32_t sb = smb + ((c & 1) ? STAGE_BYTES : 0);
        const uint32_t sA_hi = sb, sA_lo = sb + MAT_BYTES;
        const uint32_t sB_hi = sb + 2 * MAT_BYTES, sB_lo = sb + 3 * MAT_BYTES;

#pragma unroll
        for (int kk = 0; kk < 4; kk++) {
            uint32_t bh[4][2], bl[4][2];
            LDX4(bh[0][0], bh[0][1], bh[1][0], bh[1][1], sB_hi + boff + kk * 32);
            LDX4(bh[2][0], bh[2][1], bh[3][0], bh[3][1], sB_hi + boff + 16 * AR_STRIDE + kk * 32);
            LDX4(bl[0][0], bl[0][1], bl[1][0], bl[1][1], sB_lo + boff + kk * 32);
            LDX4(bl[2][0], bl[2][1], bl[3][0], bl[3][1], sB_lo + boff + 16 * AR_STRIDE + kk * 32);
#pragma unroll
            for (int i = 0; i < 4; i++) {
                uint32_t ah[4], al[4];
                LDX4(ah[0], ah[1], ah[2], ah[3], sA_hi + aoff + i * 16 * AR_STRIDE + kk * 32);
                LDX4(al[0], al[1], al[2], al[3], sA_lo + aoff + i * 16 * AR_STRIDE + kk * 32);
#pragma unroll
                for (int j = 0; j < 4; j++) {
                    mma16816(acc[i][j], ah, bh[j]);
                    mma16816(acc[i][j], ah, bl[j]);
                    mma16816(acc[i][j], al, bh[j]);
                }
            }
        }
        __syncthreads();
    }
#undef LOAD_STAGE

    // ---- epilogue ----
    const int gid = lane >> 2, tg = lane & 3;
#pragma unroll
    for (int i = 0; i < 4; i++) {
#pragma unroll
        for (int j = 0; j < 4; j++) {
            int row0 = m0 + mw * 64 + i * 16 + gid;
            int row1 = row0 + 8;
            int col = n0 + nw * 32 + j * 8 + tg * 2;
            float b0v = bias[col], b1v = bias[col + 1];
            float v00 = acc[i][j][0] + b0v, v01 = acc[i][j][1] + b1v;
            float v10 = acc[i][j][2] + b0v, v11 = acc[i][j][3] + b1v;
            if (mode == 0) {
                if (res) {
                    float2 r0 = *(const float2*)(res + (size_t)row0 * ldo + col);
                    float2 r1 = *(const float2*)(res + (size_t)row1 * ldo + col);
                    v00 += r0.x; v01 += r0.y; v10 += r1.x; v11 += r1.y;
                }
                if (relu) {
                    v00 = fmaxf(v00, 0.f); v01 = fmaxf(v01, 0.f);
                    v10 = fmaxf(v10, 0.f); v11 = fmaxf(v11, 0.f);
                }
                *(float2*)(outp + (size_t)row0 * ldo + col) = make_float2(v00, v01);
                *(float2*)(outp + (size_t)row1 * ldo + col) = make_float2(v10, v11);
            } else if (mode == 1) {
                const int z = col >> 9, hh = (col >> 6) & 7, d0 = col & 63;
                float* O = (z == 0) ? Oq : (z == 1 ? Ok : Ov);
                int b0i = row0 >> 7, t0 = row0 & 127;
                int b1i = row1 >> 7, t1 = row1 & 127;
                *(float2*)(O + (((size_t)(b0i * HH + hh)) * TT + t0) * DHH + d0) = make_float2(v00, v01);
                *(float2*)(O + (((size_t)(b1i * HH + hh)) * TT + t1) * DHH + d0) = make_float2(v10, v11);
            } else {
                if (relu) {
                    v00 = fmaxf(v00, 0.f); v01 = fmaxf(v01, 0.f);
                    v10 = fmaxf(v10, 0.f); v11 = fmaxf(v11, 0.f);
                }
                uint32_t h00, l00, h01, l01, h10, l10, h11, l11;
                split1(v00, h00, l00); split1(v01, h01, l01);
                split1(v10, h10, l10); split1(v11, h11, l11);
                *(uint32_t*)(ohi + (size_t)row0 * ldo + col) = h00 | (h01 << 16);
                *(uint32_t*)(olo + (size_t)row0 * ldo + col) = l00 | (l01 << 16);
                *(uint32_t*)(ohi + (size_t)row1 * ldo + col) = h10 | (h11 << 16);
                *(uint32_t*)(olo + (size_t)row1 * ldo + col) = l10 | (l11 << 16);
            }
        }
    }
}

// =============================================================================
// Weight prep: transpose fp32 weights into K-major bf16 hi/lo [N,K]
// =============================================================================
__global__ __launch_bounds__(256) void prep_qkv(
    const float* __restrict__ wq, const float* __restrict__ wk, const float* __restrict__ wv,
    const float* __restrict__ bq, const float* __restrict__ bk, const float* __restrict__ bv,
    bf16* __restrict__ whi, bf16* __restrict__ wlo, float* __restrict__ gb)
{
    __shared__ float smt[64][65];
    const int tid = threadIdx.x;
    const int c0 = blockIdx.x * 64;
    const int nb0 = blockIdx.y * 64;
    const int z = nb0 >> 9, hh = (nb0 >> 6) & 7;
    const float* W = ((z == 0) ? wq : (z == 1 ? wk : wv)) + (size_t)hh * CC * DHH;

#pragma unroll
    for (int p = 0; p < 4; p++) {
        int v = p * 256 + tid;
        int ci = v >> 4, q = v & 15;
        float4 a = *(const float4*)(W + (size_t)(c0 + ci) * DHH + q * 4);
        smt[ci][q * 4 + 0] = a.x; smt[ci][q * 4 + 1] = a.y;
        smt[ci][q * 4 + 2] = a.z; smt[ci][q * 4 + 3] = a.w;
    }
    __syncthreads();
#pragma unroll
    for (int p = 0; p < 2; p++) {
        int u = p * 256 + tid;
        int d = u >> 3, cv = u & 7;
        uint4 uh, ul;
        uint32_t* ph = (uint32_t*)&uh;
        uint32_t* pl = (uint32_t*)&ul;
#pragma unroll
        for (int j = 0; j < 4; j++) {
            uint32_t h0, l0, h1, l1;
            split1(smt[cv * 8 + 2 * j][d], h0, l0);
            split1(smt[cv * 8 + 2 * j + 1][d], h1, l1);
            ph[j] = h0 | (h1 << 16);
            pl[j] = l0 | (l1 << 16);
        }
        size_t o = (size_t)(nb0 + d) * CC + c0 + cv * 8;
        *(uint4*)(whi + o) = uh;
        *(uint4*)(wlo + o) = ul;
    }
    if (blockIdx.x == 0 && tid < 64) {
        const float* bsrc = (z == 0) ? bq : (z == 1 ? bk : bv);
        gb[nb0 + tid] = bsrc[hh * DHH + tid];
    }
}

__global__ __launch_bounds__(256) void prep_plain(
    const float* __restrict__ W, int Kd, int Nd,
    bf16* __restrict__ whi, bf16* __restrict__ wlo)
{
    __shared__ float smt[64][65];
    const int tid = threadIdx.x;
    const int c0 = blockIdx.x * 64;
    const int nb0 = blockIdx.y * 64;

#pragma unroll
    for (int p = 0; p < 4; p++) {
        int v = p * 256 + tid;
        int ci = v >> 4, q = v & 15;
        float4 a = *(const float4*)(W + (size_t)(c0 + ci) * Nd + nb0 + q * 4);
        smt[ci][q * 4 + 0] = a.x; smt[ci][q * 4 + 1] = a.y;
        smt[ci][q * 4 + 2] = a.z; smt[ci][q * 4 + 3] = a.w;
    }
    __syncthreads();
#pragma unroll
    for (int p = 0; p < 2; p++) {
        int u = p * 256 + tid;
        int d = u >> 3, cv = u & 7;
        uint4 uh, ul;
        uint32_t* ph = (uint32_t*)&uh;
        uint32_t* pl = (uint32_t*)&ul;
#pragma unroll
        for (int j = 0; j < 4; j++) {
            uint32_t h0, l0, h1, l1;
            split1(smt[cv * 8 + 2 * j][d], h0, l0);
            split1(smt[cv * 8 + 2 * j + 1][d], h1, l1);
            ph[j] = h0 | (h1 << 16);
            pl[j] = l0 | (l1 << 16);
        }
        size_t o = (size_t)(nb0 + d) * Kd + c0 + cv * 8;
        *(uint4*)(whi + o) = uh;
        *(uint4*)(wlo + o) = ul;
    }
}

// ---- standalone fp32 -> bf16 hi/lo split (for x_in and encoder_output) ------
__global__ __launch_bounds__(256) void conv_split(
    const float* __restrict__ a, bf16* __restrict__ hi, bf16* __restrict__ lo, int n8)
{
    for (int i = blockIdx.x * 256 + threadIdx.x; i < n8; i += gridDim.x * 256) {
        float4 v0 = *(const float4*)(a + (size_t)i * 8);
        float4 v1 = *(const float4*)(a + (size_t)i * 8 + 4);
        uint4 uh, ul;
        uint32_t* ph = (uint32_t*)&uh;
        uint32_t* pl = (uint32_t*)&ul;
        const float* vv = (const float*)&v0;
#pragma unroll
        for (int j = 0; j < 4; j++) {
            float x0 = (j < 2) ? ((const float*)&v0)[2 * j] : ((const float*)&v1)[2 * (j - 2)];
            float x1 = (j < 2) ? ((const float*)&v0)[2 * j + 1] : ((const float*)&v1)[2 * (j - 2) + 1];
            uint32_t h0, l0v, h1, l1v;
            split1(x0, h0, l0v); split1(x1, h1, l1v);
            ph[j] = h0 | (h1 << 16);
            pl[j] = l0v | (l1v << 16);
        }
        (void)vv;
        *(uint4*)(hi + (size_t)i * 8) = uh;
        *(uint4*)(lo + (size_t)i * 8) = ul;
    }
}

// =============================================================================
// Attention: one CTA per (b,h). 128 threads, thread t owns query row t.
// =============================================================================
__global__ __launch_bounds__(128) void attn_kernel(
    const float* __restrict__ Q, const float* __restrict__ K,
    const float* __restrict__ V, float* __restrict__ outp)
{
    extern __shared__ float smf[];
    float* KV = smf;
    float* P = smf + TT * DHH;

    const int bh = blockIdx.x;
    const int t = threadIdx.x;
    const size_t base = (size_t)bh * TT * DHH;
    const float* Qp = Q + base;
    const float* Kp = K + base;
    const float* Vp = V + base;

    for (int i = t * 4; i < TT * DHH; i += 128 * 4)
        *(float4*)&KV[i] = *(const float4*)&Kp[i];

    ulonglong2 q2[16];
    const ulonglong2* qsrc = (const ulonglong2*)(Qp + (size_t)t * DHH);
#pragma unroll
    for (int i = 0; i < 16; i++) q2[i] = qsrc[i];
    __syncthreads();

    float* Prow = P + t * 129;
    float mx = -1e30f;
    for (int s = 0; s < SS; s++) {
        const ulonglong2* kp2 = (const ulonglong2*)(KV + s * DHH);
        ull a0 = 0, a1 = 0, a2v = 0, a3 = 0;
#pragma unroll
        for (int i = 0; i < 16; i += 2) {
            ulonglong2 kv0 = kp2[i], kv1 = kp2[i + 1];
            a0 = ffma2(q2[i].x, kv0.x, a0);
            a1 = ffma2(q2[i].y, kv0.y, a1);
            a2v = ffma2(q2[i + 1].x, kv1.x, a2v);
            a3 = ffma2(q2[i + 1].y, kv1.y, a3);
        }
        float2 f0 = unpack2(a0), f1 = unpack2(a1), f2 = unpack2(a2v), f3 = unpack2(a3);
        float dot = ((f0.x + f0.y) + (f1.x + f1.y)) + ((f2.x + f2.y) + (f3.x + f3.y));
        Prow[s] = dot;
        mx = fmaxf(mx, dot);
    }
    float sum = 0.f;
    for (int s = 0; s < SS; s++) {
        float e = __expf(0.125f * (Prow[s] - mx));
        Prow[s] = e;
        sum += e;
    }
    float inv = 1.f / sum;

    __syncthreads();
    for (int i = t * 4; i < TT * DHH; i += 128 * 4)
        *(float4*)&KV[i] = *(const float4*)&Vp[i];
    __syncthreads();

    ull o2[32];
#pragma unroll
    for (int i = 0; i < 32; i++) o2[i] = 0ull;
    for (int s = 0; s < SS; s++) {
        ull p2 = splat2(Prow[s]);
        const ulonglong2* vp2 = (const ulonglong2*)(KV + s * DHH);
#pragma unroll
        for (int i = 0; i < 16; i++) {
            ulonglong2 vv = vp2[i];
            o2[2 * i]     = ffma2(p2, vv.x, o2[2 * i]);
            o2[2 * i + 1] = ffma2(p2, vv.y, o2[2 * i + 1]);
        }
    }

    const int b = bh / HH, h = bh % HH;
    float* op = outp + ((size_t)b * TT + t) * CC + h * DHH;
#pragma unroll
    for (int j = 0; j < 32; j++) {
        float2 f = unpack2(o2[j]);
        op[2 * j]     = f.x * inv;
        op[2 * j + 1] = f.y * inv;
    }
}

// =============================================================================
// Two-pass joint (T,C) LayerNorm.  Pass 1: partial sums, grid (B, 8).
// Pass 2: normalize + write fp32 + bf16 hi/lo split, grid (B, 8).
// =============================================================================
__global__ __launch_bounds__(256) void ln_part1(
    const float* __restrict__ a, const float* __restrict__ r, float* __restrict__ red)
{
    const int b = blockIdx.x, ch = blockIdx.y;
    const size_t base = (size_t)b * (TT * CC) + (size_t)ch * 8192;
    const float4* pa = (const float4*)(a + base);
    const float4* pr = r ? (const float4*)(r + base) : nullptr;

    float s = 0.f, ss = 0.f;
    for (int i = threadIdx.x; i < 2048; i += 256) {
        float4 v = pa[i];
        if (pr) { float4 w = pr[i]; v.x += w.x; v.y += w.y; v.z += w.z; v.w += w.w; }
        s += (v.x + v.y) + (v.z + v.w);
        ss += (v.x * v.x + v.y * v.y) + (v.z * v.z + v.w * v.w);
    }
#pragma unroll
    for (int o = 16; o > 0; o >>= 1) {
        s += __shfl_down_sync(0xffffffffu, s, o);
        ss += __shfl_down_sync(0xffffffffu, ss, o);
    }
    __shared__ float rs[8], rss[8];
    const int w = threadIdx.x >> 5;
    if ((threadIdx.x & 31) == 0) { rs[w] = s; rss[w] = ss; }
    __syncthreads();
    if (threadIdx.x == 0) {
        float S = 0.f, SS2 = 0.f;
        for (int i = 0; i < 8; i++) { S += rs[i]; SS2 += rss[i]; }
        red[(b * 8 + ch) * 2 + 0] = S;
        red[(b * 8 + ch) * 2 + 1] = SS2;
    }
}

__global__ __launch_bounds__(256) void ln_part2(
    const float* __restrict__ a, const float* __restrict__ r,
    float* __restrict__ outp, bf16* __restrict__ ohi, bf16* __restrict__ olo,
    const float* __restrict__ red)
{
    const int b = blockIdx.x, ch = blockIdx.y;
    float S = 0.f, SS2 = 0.f;
#pragma unroll
    for (int i = 0; i < 8; i++) {
        S += red[(b * 8 + i) * 2 + 0];
        SS2 += red[(b * 8 + i) * 2 + 1];
    }
    const float N = (float)(TT * CC);
    const float mu = S / N;
    const float rsig = rsqrtf(SS2 / N - mu * mu + LN_EPS);

    const size_t base = (size_t)b * (TT * CC) + (size_t)ch * 8192;
    const float4* pa = (const float4*)(a + base);
    const float4* pr = r ? (const float4*)(r + base) : nullptr;
    float4* po = (float4*)(outp + base);
    for (int i = threadIdx.x; i < 2048; i += 256) {
        float4 v = pa[i];
        if (pr) { float4 w = pr[i]; v.x += w.x; v.y += w.y; v.z += w.z; v.w += w.w; }
        v.x = (v.x - mu) * rsig;
        v.y = (v.y - mu) * rsig;
        v.z = (v.z - mu) * rsig;
        v.w = (v.w - mu) * rsig;
        po[i] = v;
        uint32_t h0, l0, h1, l1, h2, l2, h3, l3;
        split1(v.x, h0, l0); split1(v.y, h1, l1);
        split1(v.z, h2, l2); split1(v.w, h3, l3);
        uint2 uh = make_uint2(h0 | (h1 << 16), h2 | (h3 << 16));
        uint2 ul = make_uint2(l0 | (l1 << 16), l2 | (l3 << 16));
        *(uint2*)(ohi + base + (size_t)i * 4) = uh;
        *(uint2*)(olo + base + (size_t)i * 4) = ul;
    }
}

// =============================================================================
extern "C" void kernel_launch(void* const* d_in, const int* in_sizes, int n_in,
                              void* d_out, int out_size)
{
    (void)in_sizes; (void)n_in; (void)out_size;

    const float* x_in  = (const float*)d_in[0];
    const float* enc   = (const float*)d_in[1];
    const float* sa_wq = (const float*)d_in[2];
    const float* sa_bq = (const float*)d_in[3];
    const float* sa_wk = (const float*)d_in[4];
    const float* sa_bk = (const float*)d_in[5];
    const float* sa_wv = (const float*)d_in[6];
    const float* sa_bv = (const float*)d_in[7];
    const float* ca_wq = (const float*)d_in[8];
    const float* ca_bq = (const float*)d_in[9];
    const float* ca_wk = (const float*)d_in[10];
    const float* ca_bk = (const float*)d_in[11];
    const float* ca_wv = (const float*)d_in[12];
    const float* ca_bv = (const float*)d_in[13];
    const float* ff_w1 = (const float*)d_in[14];
    const float* ff_b1 = (const float*)d_in[15];
    const float* ff_w2 = (const float*)d_in[16];
    const float* ff_b2 = (const float*)d_in[17];

    float *gx, *gq, *gk, *gv, *gatt, *gb, *gred;
    bf16 *gxhi, *gxlo, *gehi, *gelo, *ghhi, *ghlo, *gwhi, *gwlo;
    cudaGetSymbolAddress((void**)&gx, g_x);
    cudaGetSymbolAddress((void**)&gq, g_q);
    cudaGetSymbolAddress((void**)&gk, g_k);
    cudaGetSymbolAddress((void**)&gv, g_v);
    cudaGetSymbolAddress((void**)&gatt, g_att);
    cudaGetSymbolAddress((void**)&gxhi, g_xhi);
    cudaGetSymbolAddress((void**)&gxlo, g_xlo);
    cudaGetSymbolAddress((void**)&gehi, g_ehi);
    cudaGetSymbolAddress((void**)&gelo, g_elo);
    cudaGetSymbolAddress((void**)&ghhi, g_hhi);
    cudaGetSymbolAddress((void**)&ghlo, g_hlo);
    cudaGetSymbolAddress((void**)&gwhi, g_whi);
    cudaGetSymbolAddress((void**)&gwlo, g_wlo);
    cudaGetSymbolAddress((void**)&gb, g_bias);
    cudaGetSymbolAddress((void**)&gred, g_red);

    const int attn_smem = (TT * DHH + TT * 129) * (int)sizeof(float);
    cudaFuncSetAttribute(attn_kernel, cudaFuncAttributeMaxDynamicSharedMemorySize, attn_smem);
    cudaFuncSetAttribute(gemm_mma, cudaFuncAttributeMaxDynamicSharedMemorySize, GEMM_SMEM);

    cudaMemcpyAsync(gx, x_in, sizeof(float) * BB * TT * CC, cudaMemcpyDeviceToDevice);
    conv_split<<<296, 256>>>(x_in, gxhi, gxlo, BB * TT * CC / 8);
    conv_split<<<296, 256>>>(enc, gehi, gelo, BB * SS * CC / 8);

    for (int l = 0; l < LL; l++) {
        const size_t woff = (size_t)l * HH * CC * DHH;
        const size_t boff = (size_t)l * HH * DHH;

        // ---- self attention ----
        prep_qkv<<<dim3(8, 24), 256>>>(sa_wq + woff, sa_wk + woff, sa_wv + woff,
                                       sa_bq + boff, sa_bk + boff, sa_bv + boff,
                                       gwhi, gwlo, gb);
        gemm_mma<<<dim3(64, 12), 256, GEMM_SMEM>>>(
            gxhi, gxlo, gxhi, gxlo, CC, gwhi, gwlo, gb, nullptr,
            nullptr, nullptr, nullptr, 0, gq, gk, gv, 0, 1);
        attn_kernel<<<BB * HH, 128, attn_smem>>>(gq, gk, gv, gatt);
        ln_part1<<<dim3(BB, 8), 256>>>(gx, gatt, gred);
        ln_part2<<<dim3(BB, 8), 256>>>(gx, gatt, gx, gxhi, gxlo, gred);

        // ---- cross attention ----
        prep_qkv<<<dim3(8, 24), 256>>>(ca_wq + woff, ca_wk + woff, ca_wv + woff,
                                       ca_bq + boff, ca_bk + boff, ca_bv + boff,
                                       gwhi, gwlo, gb);
        gemm_mma<<<dim3(64, 12), 256, GEMM_SMEM>>>(
            gxhi, gxlo, gehi, gelo, CC, gwhi, gwlo, gb, nullptr,
            nullptr, nullptr, nullptr, 0, gq, gk, gv, 0, 1);
        attn_kernel<<<BB * HH, 128, attn_smem>>>(gq, gk, gv, gatt);
        ln_part1<<<dim3(BB, 8), 256>>>(gx, gatt, gred);
        ln_part2<<<dim3(BB, 8), 256>>>(gx, gatt, gx, gxhi, gxlo, gred);

        // ---- feed forward ----
        prep_plain<<<dim3(8, 32), 256>>>(ff_w1 + (size_t)l * CC * FFF, CC, FFF, gwhi, gwlo);
        gemm_mma<<<dim3(64, 16), 256, GEMM_SMEM>>>(
            gxhi, gxlo, gxhi, gxlo, CC, gwhi, gwlo, ff_b1 + (size_t)l * FFF, nullptr,
            nullptr, ghhi, ghlo, FFF, nullptr, nullptr, nullptr, 1, 2);
        prep_plain<<<dim3(32, 8), 256>>>(ff_w2 + (size_t)l * FFF * CC, FFF, CC, gwhi, gwlo);
        gemm_mma<<<dim3(64, 4), 256, GEMM_SMEM>>>(
            ghhi, ghlo, ghhi, ghlo, FFF, gwhi, gwlo, ff_b2 + (size_t)l * CC, gx,
            gatt, nullptr, nullptr, CC, nullptr, nullptr, nullptr, 0, 0);
        ln_part1<<<dim3(BB, 8), 256>>>(gatt, nullptr, gred);
        ln_part2<<<dim3(BB, 8), 256>>>(gatt, nullptr, gx, gxhi, gxlo, gred);
    }

    cudaMemcpyAsync(d_out, gx, sizeof(float) * BB * TT * CC, cudaMemcpyDeviceToDevice);
}

// round 12
// speedup vs baseline: 2.0698x; 1.0260x over previous
#include <cuda_runtime.h>
#include <cuda_bf16.h>
#include <cstdint>

// Problem dims
#define BB 64
#define TT 128
#define SS 128
#define CC 512
#define HH 8
#define DHH 64
#define FFF 2048
#define LL 6
#define LN_EPS 1e-5f

typedef unsigned long long ull;
typedef __nv_bfloat16 bf16;

// ---------------- scratch (static device allocations — allowed) --------------
__device__ float g_x[BB * TT * CC];
__device__ float g_q[BB * HH * TT * DHH];
__device__ float g_k[BB * HH * TT * DHH];
__device__ float g_v[BB * HH * TT * DHH];
__device__ float g_att[BB * TT * CC];
__device__ bf16 g_xhi[BB * TT * CC];          // split activations (decoder x)
__device__ bf16 g_xlo[BB * TT * CC];
__device__ bf16 g_ehi[BB * SS * CC];          // split encoder output
__device__ bf16 g_elo[BB * SS * CC];
__device__ bf16 g_hhi[BB * TT * FFF];         // split ff hidden
__device__ bf16 g_hlo[BB * TT * FFF];
__device__ bf16 g_whi[2048 * 512];            // prepped weights (max N*K = 1M)
__device__ bf16 g_wlo[2048 * 512];
__device__ float g_bias[2048];
__device__ float g_red[BB * 8 * 2];           // LN partial sums

// ---------------- packed f32x2 helpers ---------------------------------------
__device__ __forceinline__ ull ffma2(ull a, ull b, ull c) {
    ull d; asm("fma.rn.f32x2 %0, %1, %2, %3;" : "=l"(d) : "l"(a), "l"(b), "l"(c));
    return d;
}
__device__ __forceinline__ ull splat2(float x) {
    ull d; asm("mov.b64 %0, {%1, %1};" : "=l"(d) : "f"(x)); return d;
}
__device__ __forceinline__ float2 unpack2(ull v) {
    float2 r; asm("mov.b64 {%0, %1}, %2;" : "=f"(r.x), "=f"(r.y) : "l"(v)); return r;
}
__device__ __forceinline__ uint32_t smem_u32(const void* p) {
    uint32_t a;
    asm("{ .reg .u64 t; cvta.to.shared.u64 t, %1; cvt.u32.u64 %0, t; }" : "=r"(a) : "l"(p));
    return a;
}
__device__ __forceinline__ uint32_t bfu(bf16 v) {
    return (uint32_t)__bfloat16_as_ushort(v);
}
// split one fp32 -> hi/lo bf16 pair
__device__ __forceinline__ void split1(float x, uint32_t& hi, uint32_t& lo) {
    bf16 h = __float2bfloat16_rn(x);
    hi = bfu(h);
    lo = bfu(__float2bfloat16_rn(x - __bfloat162float(h)));
}

// ---------------- mma.sync / ldmatrix / cp.async (plain-sm_103 PTX) ----------
#define LDX4(r0, r1, r2, r3, addr) \
    asm volatile("ldmatrix.sync.aligned.m8n8.x4.shared.b16 {%0,%1,%2,%3}, [%4];" \
                 : "=r"(r0), "=r"(r1), "=r"(r2), "=r"(r3) : "r"(addr))

__device__ __forceinline__ void mma16816(float* c, const uint32_t* a, const uint32_t* b) {
    asm volatile(
        "mma.sync.aligned.m16n8k16.row.col.f32.bf16.bf16.f32 "
        "{%0,%1,%2,%3}, {%4,%5,%6,%7}, {%8,%9}, {%0,%1,%2,%3};"
        : "+f"(c[0]), "+f"(c[1]), "+f"(c[2]), "+f"(c[3])
        : "r"(a[0]), "r"(a[1]), "r"(a[2]), "r"(a[3]), "r"(b[0]), "r"(b[1]));
}
__device__ __forceinline__ void cpasync16(uint32_t dst, const void* src) {
    asm volatile("cp.async.cg.shared.global [%0], [%1], 16;" :: "r"(dst), "l"(src));
}

// =============================================================================
// HMMA split-bf16 GEMM, cp.async double-buffered, 2 CTAs/SM.
// CTA tile 128x128, BK=32, 8 warps (2x4), warp tile 64x32, 3-term compensation.
// All operands pre-split bf16, K-major rows. smem rows: 32 halves = 64B padded
// to 80B stride (16B-aligned for ldmatrix!; 8 rows*80 mod 128 =
// {0,80,32,112,64,16,96,48} -> all distinct 16B banks, conflict-free).
// mode: 0 = fp32 out (+res,+relu)   1 = qkv scatter   2 = bf16 hi/lo out (+relu)
// =============================================================================
#define AR_STRIDE 80
#define MAT_BYTES (128 * AR_STRIDE)           // 10240
#define STAGE_BYTES (4 * MAT_BYTES)           // 40960
#define GEMM_SMEM (2 * STAGE_BYTES)           // 81920 -> 2 CTAs/SM (163840/SM)

__global__ __launch_bounds__(256, 2) void gemm_mma(
    const bf16* __restrict__ Aq_hi, const bf16* __restrict__ Aq_lo,
    const bf16* __restrict__ Akv_hi, const bf16* __restrict__ Akv_lo, int Kdim,
    const bf16* __restrict__ Whi, const bf16* __restrict__ Wlo,
    const float* __restrict__ bias, const float* __restrict__ res,
    float* __restrict__ outp, bf16* __restrict__ ohi, bf16* __restrict__ olo, int ldo,
    float* __restrict__ Oq, float* __restrict__ Ok, float* __restrict__ Ov,
    int relu, int mode)
{
    extern __shared__ char sm[];
    const uint32_t smb = smem_u32(sm);
    const int tid = threadIdx.x;
    const int wid = tid >> 5, lane = tid & 31;
    const int mw = wid >> 2, nw = wid & 3;

    const int m0 = blockIdx.x * 128;
    const int n0 = blockIdx.y * 128;
    const bf16 *Ahp, *Alp;
    if (mode == 1 && n0 >= 512) { Ahp = Akv_hi; Alp = Akv_lo; }
    else                        { Ahp = Aq_hi;  Alp = Aq_lo; }

    // per-thread load slots: v = p*256+tid -> row = v>>2 (0..127), cc = v&3
    // global element offset: row*Kdim + cc*8 ; smem byte offset: row*80 + cc*16
    const int r0v = tid >> 2, c0v = tid & 3;
    const int r1v = (256 + tid) >> 2, c1v = (256 + tid) & 3;
    const bf16* pAh = Ahp + (size_t)(m0 + r0v) * Kdim + c0v * 8;
    const bf16* pAl = Alp + (size_t)(m0 + r0v) * Kdim + c0v * 8;
    const bf16* pBh = Whi + (size_t)(n0 + r0v) * Kdim + c0v * 8;
    const bf16* pBl = Wlo + (size_t)(n0 + r0v) * Kdim + c0v * 8;
    const size_t d1 = (size_t)(r1v - r0v) * Kdim + (c1v - c0v) * 8;
    const uint32_t so0 = r0v * AR_STRIDE + c0v * 16;
    const uint32_t so1 = r1v * AR_STRIDE + c1v * 16;

    float acc[4][4][4];
#pragma unroll
    for (int i = 0; i < 4; i++)
#pragma unroll
        for (int j = 0; j < 4; j++)
#pragma unroll
            for (int r = 0; r < 4; r++) acc[i][j][r] = 0.f;

    // ldmatrix per-lane offsets (relative to stage base)
    const int aoff = (mw * 64 + (lane & 15)) * AR_STRIDE + (lane >> 4) * 16;
    const int mi = lane >> 3;
    const int n_off = ((mi >> 1) * 8) + (lane & 7);
    const int k_off = (mi & 1) * 8;
    const int boff = (nw * 32 + n_off) * AR_STRIDE + k_off * 2;

    const int nch = Kdim >> 5;

#define LOAD_STAGE(cidx) do {                                                  \
        const uint32_t dstb = smb + (((cidx) & 1) ? STAGE_BYTES : 0);          \
        const int kc = (cidx) << 5;                                            \
        cpasync16(dstb + so0,                 pAh + kc);                       \
        cpasync16(dstb + so1,                 pAh + kc + d1);                  \
        cpasync16(dstb + MAT_BYTES + so0,     pAl + kc);                       \
        cpasync16(dstb + MAT_BYTES + so1,     pAl + kc + d1);                  \
        cpasync16(dstb + 2 * MAT_BYTES + so0, pBh + kc);                       \
        cpasync16(dstb + 2 * MAT_BYTES + so1, pBh + kc + d1);                  \
        cpasync16(dstb + 3 * MAT_BYTES + so0, pBl + kc);                       \
        cpasync16(dstb + 3 * MAT_BYTES + so1, pBl + kc + d1);                  \
        asm volatile("cp.async.commit_group;");                                \
    } while (0)

    LOAD_STAGE(0);

    for (int c = 0; c < nch; c++) {
        if (c + 1 < nch) {
            LOAD_STAGE(c + 1);
            asm volatile("cp.async.wait_group 1;");
        } else {
            asm volatile("cp.async.wait_group 0;");
        }
        __syncthreads();

        const uint32_t sb = smb + ((c & 1) ? STAGE_BYTES : 0);
        const uint32_t sA_hi = sb, sA_lo = sb + MAT_BYTES;
        const uint32_t sB_hi = sb + 2 * MAT_BYTES, sB_lo = sb + 3 * MAT_BYTES;

#pragma unroll
        for (int kk = 0; kk < 2; kk++) {
            uint32_t bh[4][2], bl[4][2];
            LDX4(bh[0][0], bh[0][1], bh[1][0], bh[1][1], sB_hi + boff + kk * 32);
            LDX4(bh[2][0], bh[2][1], bh[3][0], bh[3][1], sB_hi + boff + 16 * AR_STRIDE + kk * 32);
            LDX4(bl[0][0], bl[0][1], bl[1][0], bl[1][1], sB_lo + boff + kk * 32);
            LDX4(bl[2][0], bl[2][1], bl[3][0], bl[3][1], sB_lo + boff + 16 * AR_STRIDE + kk * 32);
#pragma unroll
            for (int i = 0; i < 4; i++) {
                uint32_t ah[4], al[4];
                LDX4(ah[0], ah[1], ah[2], ah[3], sA_hi + aoff + i * 16 * AR_STRIDE + kk * 32);
                LDX4(al[0], al[1], al[2], al[3], sA_lo + aoff + i * 16 * AR_STRIDE + kk * 32);
#pragma unroll
                for (int j = 0; j < 4; j++) {
                    mma16816(acc[i][j], ah, bh[j]);
                    mma16816(acc[i][j], ah, bl[j]);
                    mma16816(acc[i][j], al, bh[j]);
                }
            }
        }
        __syncthreads();
    }
#undef LOAD_STAGE

    // ---- epilogue ----
    const int gid = lane >> 2, tg = lane & 3;
#pragma unroll
    for (int i = 0; i < 4; i++) {
#pragma unroll
        for (int j = 0; j < 4; j++) {
            int row0 = m0 + mw * 64 + i * 16 + gid;
            int row1 = row0 + 8;
            int col = n0 + nw * 32 + j * 8 + tg * 2;
            float b0v = bias[col], b1v = bias[col + 1];
            float v00 = acc[i][j][0] + b0v, v01 = acc[i][j][1] + b1v;
            float v10 = acc[i][j][2] + b0v, v11 = acc[i][j][3] + b1v;
            if (mode == 0) {
                if (res) {
                    float2 r0 = *(const float2*)(res + (size_t)row0 * ldo + col);
                    float2 r1 = *(const float2*)(res + (size_t)row1 * ldo + col);
                    v00 += r0.x; v01 += r0.y; v10 += r1.x; v11 += r1.y;
                }
                if (relu) {
                    v00 = fmaxf(v00, 0.f); v01 = fmaxf(v01, 0.f);
                    v10 = fmaxf(v10, 0.f); v11 = fmaxf(v11, 0.f);
                }
                *(float2*)(outp + (size_t)row0 * ldo + col) = make_float2(v00, v01);
                *(float2*)(outp + (size_t)row1 * ldo + col) = make_float2(v10, v11);
            } else if (mode == 1) {
                const int z = col >> 9, hh = (col >> 6) & 7, d0 = col & 63;
                float* O = (z == 0) ? Oq : (z == 1 ? Ok : Ov);
                int b0i = row0 >> 7, t0 = row0 & 127;
                int b1i = row1 >> 7, t1 = row1 & 127;
                *(float2*)(O + (((size_t)(b0i * HH + hh)) * TT + t0) * DHH + d0) = make_float2(v00, v01);
                *(float2*)(O + (((size_t)(b1i * HH + hh)) * TT + t1) * DHH + d0) = make_float2(v10, v11);
            } else {
                if (relu) {
                    v00 = fmaxf(v00, 0.f); v01 = fmaxf(v01, 0.f);
                    v10 = fmaxf(v10, 0.f); v11 = fmaxf(v11, 0.f);
                }
                uint32_t h00, l00, h01, l01, h10, l10, h11, l11;
                split1(v00, h00, l00); split1(v01, h01, l01);
                split1(v10, h10, l10); split1(v11, h11, l11);
                *(uint32_t*)(ohi + (size_t)row0 * ldo + col) = h00 | (h01 << 16);
                *(uint32_t*)(olo + (size_t)row0 * ldo + col) = l00 | (l01 << 16);
                *(uint32_t*)(ohi + (size_t)row1 * ldo + col) = h10 | (h11 << 16);
                *(uint32_t*)(olo + (size_t)row1 * ldo + col) = l10 | (l11 << 16);
            }
        }
    }
}

// =============================================================================
// Weight prep: transpose fp32 weights into K-major bf16 hi/lo [N,K]
// =============================================================================
__global__ __launch_bounds__(256) void prep_qkv(
    const float* __restrict__ wq, const float* __restrict__ wk, const float* __restrict__ wv,
    const float* __restrict__ bq, const float* __restrict__ bk, const float* __restrict__ bv,
    bf16* __restrict__ whi, bf16* __restrict__ wlo, float* __restrict__ gb)
{
    __shared__ float smt[64][65];
    const int tid = threadIdx.x;
    const int c0 = blockIdx.x * 64;
    const int nb0 = blockIdx.y * 64;
    const int z = nb0 >> 9, hh = (nb0 >> 6) & 7;
    const float* W = ((z == 0) ? wq : (z == 1 ? wk : wv)) + (size_t)hh * CC * DHH;

#pragma unroll
    for (int p = 0; p < 4; p++) {
        int v = p * 256 + tid;
        int ci = v >> 4, q = v & 15;
        float4 a = *(const float4*)(W + (size_t)(c0 + ci) * DHH + q * 4);
        smt[ci][q * 4 + 0] = a.x; smt[ci][q * 4 + 1] = a.y;
        smt[ci][q * 4 + 2] = a.z; smt[ci][q * 4 + 3] = a.w;
    }
    __syncthreads();
#pragma unroll
    for (int p = 0; p < 2; p++) {
        int u = p * 256 + tid;
        int d = u >> 3, cv = u & 7;
        uint4 uh, ul;
        uint32_t* ph = (uint32_t*)&uh;
        uint32_t* pl = (uint32_t*)&ul;
#pragma unroll
        for (int j = 0; j < 4; j++) {
            uint32_t h0, l0, h1, l1;
            split1(smt[cv * 8 + 2 * j][d], h0, l0);
            split1(smt[cv * 8 + 2 * j + 1][d], h1, l1);
            ph[j] = h0 | (h1 << 16);
            pl[j] = l0 | (l1 << 16);
        }
        size_t o = (size_t)(nb0 + d) * CC + c0 + cv * 8;
        *(uint4*)(whi + o) = uh;
        *(uint4*)(wlo + o) = ul;
    }
    if (blockIdx.x == 0 && tid < 64) {
        const float* bsrc = (z == 0) ? bq : (z == 1 ? bk : bv);
        gb[nb0 + tid] = bsrc[hh * DHH + tid];
    }
}

__global__ __launch_bounds__(256) void prep_plain(
    const float* __restrict__ W, int Kd, int Nd,
    bf16* __restrict__ whi, bf16* __restrict__ wlo)
{
    __shared__ float smt[64][65];
    const int tid = threadIdx.x;
    const int c0 = blockIdx.x * 64;
    const int nb0 = blockIdx.y * 64;

#pragma unroll
    for (int p = 0; p < 4; p++) {
        int v = p * 256 + tid;
        int ci = v >> 4, q = v & 15;
        float4 a = *(const float4*)(W + (size_t)(c0 + ci) * Nd + nb0 + q * 4);
        smt[ci][q * 4 + 0] = a.x; smt[ci][q * 4 + 1] = a.y;
        smt[ci][q * 4 + 2] = a.z; smt[ci][q * 4 + 3] = a.w;
    }
    __syncthreads();
#pragma unroll
    for (int p = 0; p < 2; p++) {
        int u = p * 256 + tid;
        int d = u >> 3, cv = u & 7;
        uint4 uh, ul;
        uint32_t* ph = (uint32_t*)&uh;
        uint32_t* pl = (uint32_t*)&ul;
#pragma unroll
        for (int j = 0; j < 4; j++) {
            uint32_t h0, l0, h1, l1;
            split1(smt[cv * 8 + 2 * j][d], h0, l0);
            split1(smt[cv * 8 + 2 * j + 1][d], h1, l1);
            ph[j] = h0 | (h1 << 16);
            pl[j] = l0 | (l1 << 16);
        }
        size_t o = (size_t)(nb0 + d) * Kd + c0 + cv * 8;
        *(uint4*)(whi + o) = uh;
        *(uint4*)(wlo + o) = ul;
    }
}

// ---- standalone fp32 -> bf16 hi/lo split (for x_in and encoder_output) ------
__global__ __launch_bounds__(256) void conv_split(
    const float* __restrict__ a, bf16* __restrict__ hi, bf16* __restrict__ lo, int n8)
{
    for (int i = blockIdx.x * 256 + threadIdx.x; i < n8; i += gridDim.x * 256) {
        float4 v0 = *(const float4*)(a + (size_t)i * 8);
        float4 v1 = *(const float4*)(a + (size_t)i * 8 + 4);
        uint4 uh, ul;
        uint32_t* ph = (uint32_t*)&uh;
        uint32_t* pl = (uint32_t*)&ul;
#pragma unroll
        for (int j = 0; j < 4; j++) {
            float x0 = (j < 2) ? ((const float*)&v0)[2 * j] : ((const float*)&v1)[2 * (j - 2)];
            float x1 = (j < 2) ? ((const float*)&v0)[2 * j + 1] : ((const float*)&v1)[2 * (j - 2) + 1];
            uint32_t h0, l0v, h1, l1v;
            split1(x0, h0, l0v); split1(x1, h1, l1v);
            ph[j] = h0 | (h1 << 16);
            pl[j] = l0v | (l1v << 16);
        }
        *(uint4*)(hi + (size_t)i * 8) = uh;
        *(uint4*)(lo + (size_t)i * 8) = ul;
    }
}

// =============================================================================
// Attention: one CTA per (b,h). 128 threads, thread t owns query row t.
// =============================================================================
__global__ __launch_bounds__(128) void attn_kernel(
    const float* __restrict__ Q, const float* __restrict__ K,
    const float* __restrict__ V, float* __restrict__ outp)
{
    extern __shared__ float smf[];
    float* KV = smf;
    float* P = smf + TT * DHH;

    const int bh = blockIdx.x;
    const int t = threadIdx.x;
    const size_t base = (size_t)bh * TT * DHH;
    const float* Qp = Q + base;
    const float* Kp = K + base;
    const float* Vp = V + base;

    for (int i = t * 4; i < TT * DHH; i += 128 * 4)
        *(float4*)&KV[i] = *(const float4*)&Kp[i];

    ulonglong2 q2[16];
    const ulonglong2* qsrc = (const ulonglong2*)(Qp + (size_t)t * DHH);
#pragma unroll
    for (int i = 0; i < 16; i++) q2[i] = qsrc[i];
    __syncthreads();

    float* Prow = P + t * 129;
    float mx = -1e30f;
    for (int s = 0; s < SS; s++) {
        const ulonglong2* kp2 = (const ulonglong2*)(KV + s * DHH);
        ull a0 = 0, a1 = 0, a2v = 0, a3 = 0;
#pragma unroll
        for (int i = 0; i < 16; i += 2) {
            ulonglong2 kv0 = kp2[i], kv1 = kp2[i + 1];
            a0 = ffma2(q2[i].x, kv0.x, a0);
            a1 = ffma2(q2[i].y, kv0.y, a1);
            a2v = ffma2(q2[i + 1].x, kv1.x, a2v);
            a3 = ffma2(q2[i + 1].y, kv1.y, a3);
        }
        float2 f0 = unpack2(a0), f1 = unpack2(a1), f2 = unpack2(a2v), f3 = unpack2(a3);
        float dot = ((f0.x + f0.y) + (f1.x + f1.y)) + ((f2.x + f2.y) + (f3.x + f3.y));
        Prow[s] = dot;
        mx = fmaxf(mx, dot);
    }
    float sum = 0.f;
    for (int s = 0; s < SS; s++) {
        float e = __expf(0.125f * (Prow[s] - mx));
        Prow[s] = e;
        sum += e;
    }
    float inv = 1.f / sum;

    __syncthreads();
    for (int i = t * 4; i < TT * DHH; i += 128 * 4)
        *(float4*)&KV[i] = *(const float4*)&Vp[i];
    __syncthreads();

    ull o2[32];
#pragma unroll
    for (int i = 0; i < 32; i++) o2[i] = 0ull;
    for (int s = 0; s < SS; s++) {
        ull p2 = splat2(Prow[s]);
        const ulonglong2* vp2 = (const ulonglong2*)(KV + s * DHH);
#pragma unroll
        for (int i = 0; i < 16; i++) {
            ulonglong2 vv = vp2[i];
            o2[2 * i]     = ffma2(p2, vv.x, o2[2 * i]);
            o2[2 * i + 1] = ffma2(p2, vv.y, o2[2 * i + 1]);
        }
    }

    const int b = bh / HH, h = bh % HH;
    float* op = outp + ((size_t)b * TT + t) * CC + h * DHH;
#pragma unroll
    for (int j = 0; j < 32; j++) {
        float2 f = unpack2(o2[j]);
        op[2 * j]     = f.x * inv;
        op[2 * j + 1] = f.y * inv;
    }
}

// =============================================================================
// Two-pass joint (T,C) LayerNorm.  Pass 1: partial sums, grid (B, 8).
// Pass 2: normalize + write fp32 + bf16 hi/lo split, grid (B, 8).
// =============================================================================
__global__ __launch_bounds__(256) void ln_part1(
    const float* __restrict__ a, const float* __restrict__ r, float* __restrict__ red)
{
    const int b = blockIdx.x, ch = blockIdx.y;
    const size_t base = (size_t)b * (TT * CC) + (size_t)ch * 8192;
    const float4* pa = (const float4*)(a + base);
    const float4* pr = r ? (const float4*)(r + base) : nullptr;

    float s = 0.f, ss = 0.f;
    for (int i = threadIdx.x; i < 2048; i += 256) {
        float4 v = pa[i];
        if (pr) { float4 w = pr[i]; v.x += w.x; v.y += w.y; v.z += w.z; v.w += w.w; }
        s += (v.x + v.y) + (v.z + v.w);
        ss += (v.x * v.x + v.y * v.y) + (v.z * v.z + v.w * v.w);
    }
#pragma unroll
    for (int o = 16; o > 0; o >>= 1) {
        s += __shfl_down_sync(0xffffffffu, s, o);
        ss += __shfl_down_sync(0xffffffffu, ss, o);
    }
    __shared__ float rs[8], rss[8];
    const int w = threadIdx.x >> 5;
    if ((threadIdx.x & 31) == 0) { rs[w] = s; rss[w] = ss; }
    __syncthreads();
    if (threadIdx.x == 0) {
        float S = 0.f, SS2 = 0.f;
        for (int i = 0; i < 8; i++) { S += rs[i]; SS2 += rss[i]; }
        red[(b * 8 + ch) * 2 + 0] = S;
        red[(b * 8 + ch) * 2 + 1] = SS2;
    }
}

__global__ __launch_bounds__(256) void ln_part2(
    const float* __restrict__ a, const float* __restrict__ r,
    float* __restrict__ outp, bf16* __restrict__ ohi, bf16* __restrict__ olo,
    const float* __restrict__ red)
{
    const int b = blockIdx.x, ch = blockIdx.y;
    float S = 0.f, SS2 = 0.f;
#pragma unroll
    for (int i = 0; i < 8; i++) {
        S += red[(b * 8 + i) * 2 + 0];
        SS2 += red[(b * 8 + i) * 2 + 1];
    }
    const float N = (float)(TT * CC);
    const float mu = S / N;
    const float rsig = rsqrtf(SS2 / N - mu * mu + LN_EPS);

    const size_t base = (size_t)b * (TT * CC) + (size_t)ch * 8192;
    const float4* pa = (const float4*)(a + base);
    const float4* pr = r ? (const float4*)(r + base) : nullptr;
    float4* po = (float4*)(outp + base);
    for (int i = threadIdx.x; i < 2048; i += 256) {
        float4 v = pa[i];
        if (pr) { float4 w = pr[i]; v.x += w.x; v.y += w.y; v.z += w.z; v.w += w.w; }
        v.x = (v.x - mu) * rsig;
        v.y = (v.y - mu) * rsig;
        v.z = (v.z - mu) * rsig;
        v.w = (v.w - mu) * rsig;
        po[i] = v;
        uint32_t h0, l0, h1, l1, h2, l2, h3, l3;
        split1(v.x, h0, l0); split1(v.y, h1, l1);
        split1(v.z, h2, l2); split1(v.w, h3, l3);
        uint2 uh = make_uint2(h0 | (h1 << 16), h2 | (h3 << 16));
        uint2 ul = make_uint2(l0 | (l1 << 16), l2 | (l3 << 16));
        *(uint2*)(ohi + base + (size_t)i * 4) = uh;
        *(uint2*)(olo + base + (size_t)i * 4) = ul;
    }
}

// =============================================================================
extern "C" void kernel_launch(void* const* d_in, const int* in_sizes, int n_in,
                              void* d_out, int out_size)
{
    (void)in_sizes; (void)n_in; (void)out_size;

    const float* x_in  = (const float*)d_in[0];
    const float* enc   = (const float*)d_in[1];
    const float* sa_wq = (const float*)d_in[2];
    const float* sa_bq = (const float*)d_in[3];
    const float* sa_wk = (const float*)d_in[4];
    const float* sa_bk = (const float*)d_in[5];
    const float* sa_wv = (const float*)d_in[6];
    const float* sa_bv = (const float*)d_in[7];
    const float* ca_wq = (const float*)d_in[8];
    const float* ca_bq = (const float*)d_in[9];
    const float* ca_wk = (const float*)d_in[10];
    const float* ca_bk = (const float*)d_in[11];
    const float* ca_wv = (const float*)d_in[12];
    const float* ca_bv = (const float*)d_in[13];
    const float* ff_w1 = (const float*)d_in[14];
    const float* ff_b1 = (const float*)d_in[15];
    const float* ff_w2 = (const float*)d_in[16];
    const float* ff_b2 = (const float*)d_in[17];

    float *gx, *gq, *gk, *gv, *gatt, *gb, *gred;
    bf16 *gxhi, *gxlo, *gehi, *gelo, *ghhi, *ghlo, *gwhi, *gwlo;
    cudaGetSymbolAddress((void**)&gx, g_x);
    cudaGetSymbolAddress((void**)&gq, g_q);
    cudaGetSymbolAddress((void**)&gk, g_k);
    cudaGetSymbolAddress((void**)&gv, g_v);
    cudaGetSymbolAddress((void**)&gatt, g_att);
    cudaGetSymbolAddress((void**)&gxhi, g_xhi);
    cudaGetSymbolAddress((void**)&gxlo, g_xlo);
    cudaGetSymbolAddress((void**)&gehi, g_ehi);
    cudaGetSymbolAddress((void**)&gelo, g_elo);
    cudaGetSymbolAddress((void**)&ghhi, g_hhi);
    cudaGetSymbolAddress((void**)&ghlo, g_hlo);
    cudaGetSymbolAddress((void**)&gwhi, g_whi);
    cudaGetSymbolAddress((void**)&gwlo, g_wlo);
    cudaGetSymbolAddress((void**)&gb, g_bias);
    cudaGetSymbolAddress((void**)&gred, g_red);

    const int attn_smem = (TT * DHH + TT * 129) * (int)sizeof(float);
    cudaFuncSetAttribute(attn_kernel, cudaFuncAttributeMaxDynamicSharedMemorySize, attn_smem);
    cudaFuncSetAttribute(gemm_mma, cudaFuncAttributeMaxDynamicSharedMemorySize, GEMM_SMEM);

    cudaMemcpyAsync(gx, x_in, sizeof(float) * BB * TT * CC, cudaMemcpyDeviceToDevice);
    conv_split<<<296, 256>>>(x_in, gxhi, gxlo, BB * TT * CC / 8);
    conv_split<<<296, 256>>>(enc, gehi, gelo, BB * SS * CC / 8);

    for (int l = 0; l < LL; l++) {
        const size_t woff = (size_t)l * HH * CC * DHH;
        const size_t boff = (size_t)l * HH * DHH;

        // ---- self attention ----
        prep_qkv<<<dim3(8, 24), 256>>>(sa_wq + woff, sa_wk + woff, sa_wv + woff,
                                       sa_bq + boff, sa_bk + boff, sa_bv + boff,
                                       gwhi, gwlo, gb);
        gemm_mma<<<dim3(64, 12), 256, GEMM_SMEM>>>(
            gxhi, gxlo, gxhi, gxlo, CC, gwhi, gwlo, gb, nullptr,
            nullptr, nullptr, nullptr, 0, gq, gk, gv, 0, 1);
        attn_kernel<<<BB * HH, 128, attn_smem>>>(gq, gk, gv, gatt);
        ln_part1<<<dim3(BB, 8), 256>>>(gx, gatt, gred);
        ln_part2<<<dim3(BB, 8), 256>>>(gx, gatt, gx, gxhi, gxlo, gred);

        // ---- cross attention ----
        prep_qkv<<<dim3(8, 24), 256>>>(ca_wq + woff, ca_wk + woff, ca_wv + woff,
                                       ca_bq + boff, ca_bk + boff, ca_bv + boff,
                                       gwhi, gwlo, gb);
        gemm_mma<<<dim3(64, 12), 256, GEMM_SMEM>>>(
            gxhi, gxlo, gehi, gelo, CC, gwhi, gwlo, gb, nullptr,
            nullptr, nullptr, nullptr, 0, gq, gk, gv, 0, 1);
        attn_kernel<<<BB * HH, 128, attn_smem>>>(gq, gk, gv, gatt);
        ln_part1<<<dim3(BB, 8), 256>>>(gx, gatt, gred);
        ln_part2<<<dim3(BB, 8), 256>>>(gx, gatt, gx, gxhi, gxlo, gred);

        // ---- feed forward ----
        prep_plain<<<dim3(8, 32), 256>>>(ff_w1 + (size_t)l * CC * FFF, CC, FFF, gwhi, gwlo);
        gemm_mma<<<dim3(64, 16), 256, GEMM_SMEM>>>(
            gxhi, gxlo, gxhi, gxlo, CC, gwhi, gwlo, ff_b1 + (size_t)l * FFF, nullptr,
            nullptr, ghhi, ghlo, FFF, nullptr, nullptr, nullptr, 1, 2);
        prep_plain<<<dim3(32, 8), 256>>>(ff_w2 + (size_t)l * FFF * CC, FFF, CC, gwhi, gwlo);
        gemm_mma<<<dim3(64, 4), 256, GEMM_SMEM>>>(
            ghhi, ghlo, ghhi, ghlo, FFF, gwhi, gwlo, ff_b2 + (size_t)l * CC, gx,
            gatt, nullptr, nullptr, CC, nullptr, nullptr, nullptr, 0, 0);
        ln_part1<<<dim3(BB, 8), 256>>>(gatt, nullptr, gred);
        ln_part2<<<dim3(BB, 8), 256>>>(gatt, nullptr, gx, gxhi, gxlo, gred);
    }

    cudaMemcpyAsync(d_out, gx, sizeof(float) * BB * TT * CC, cudaMemcpyDeviceToDevice);
}